// round 5
// baseline (speedup 1.0000x reference)
#include <cuda_runtime.h>
#include <cstdint>
#include <math.h>

// ---------------- problem constants ----------------
#define BB 16
#define TT 256
#define VV 18000
#define NSLOT 30
#define LL 10
#define GG 3
#define HH 400
#define HH2 416           // K padded to NCH*32
#define NN (NSLOT*BB)     // 480
#define MM (LL*NN)        // 4800
#define H3 (3*HH)         // 1200
#define NCH 13

#define NBM_BIG 38        // ceil(4800/128)
#define NBM_H   4         // ceil(480/128) -> 512 rows
#define NBN_EMB 141       // ceil(18000/128)
#define NBN_W   10        // ceil(1200/128)

static const size_t POINTS_ELEMS = (size_t)MM * VV;

// ---------------- scratch ----------------
__device__ __align__(128) float g_dec_in[LL*NN*HH];
__device__ __align__(128) float g_gi[LL*NN*H3];
__device__ __align__(128) float g_h[LL*NN*HH];
__device__ __align__(128) float g_hprev[NN*HH];
__device__ __align__(128) float g_gh[NN*H3];
__device__ __align__(128) float g_prob[LL*NN*TT];
__device__ __align__(128) float g_ctx[LL*NN*HH];
__device__ __align__(128) float g_switch[LL*NN];

// fragment-permuted tf32 operand buffers (zero-initialized at module load)
__device__ __align__(128) uint32_t cA_dec[NBM_BIG*NCH*4096];
__device__ __align__(128) uint32_t cA_big[NBM_BIG*NCH*4096];
__device__ __align__(128) uint32_t cA_h  [NBM_H  *NCH*4096];
__device__ __align__(128) uint32_t cB_emb[NBN_EMB*NCH*4096];
__device__ __align__(128) uint32_t cB_wih[NBN_W  *NCH*4096];
__device__ __align__(128) uint32_t cB_whh[NBN_W  *NCH*4096];

// ---------------- helpers ----------------
__device__ __forceinline__ float warpMax(float v){
    #pragma unroll
    for (int o = 16; o; o >>= 1) v = fmaxf(v, __shfl_xor_sync(0xffffffffu, v, o));
    return v;
}
__device__ __forceinline__ float warpSum(float v){
    #pragma unroll
    for (int o = 16; o; o >>= 1) v += __shfl_xor_sync(0xffffffffu, v, o);
    return v;
}
__device__ __forceinline__ float sigmoidf(float x){ return 1.f / (1.f + expf(-x)); }
__device__ __forceinline__ uint32_t f2tf32(float x){
    uint32_t r;
    asm("cvt.rna.tf32.f32 %0, %1;" : "=r"(r) : "f"(x));
    return r;
}
__device__ __forceinline__ void mma_tf32(float* d, const uint32_t* a, const uint32_t* b){
    asm volatile(
        "mma.sync.aligned.m16n8k8.row.col.f32.tf32.tf32.f32 "
        "{%0,%1,%2,%3}, {%4,%5,%6,%7}, {%8,%9}, {%0,%1,%2,%3};\n"
        : "+f"(d[0]), "+f"(d[1]), "+f"(d[2]), "+f"(d[3])
        : "r"(a[0]), "r"(a[1]), "r"(a[2]), "r"(a[3]), "r"(b[0]), "r"(b[1]));
}
__device__ __forceinline__ uint32_t smem_u32(const void* p){
    uint32_t a;
    asm("{ .reg .u64 t; cvta.to.shared.u64 t, %1; cvt.u32.u64 %0, t; }" : "=r"(a) : "l"(p));
    return a;
}
__device__ __forceinline__ void cp16(uint32_t saddr, const void* g){
    asm volatile("cp.async.ca.shared.global [%0], [%1], 16;" :: "r"(saddr), "l"(g) : "memory");
}
__device__ __forceinline__ void cp_commit(){ asm volatile("cp.async.commit_group;" ::: "memory"); }
template<int W> __device__ __forceinline__ void cp_wait(){
    asm volatile("cp.async.wait_group %0;" :: "n"(W) : "memory");
}

// permuted single-element store into A-fragment buffer (128-row blocks)
__device__ __forceinline__ void storeA(uint32_t* dst, int r, int k, float v){
    int blk = r >> 7, rl = r & 127;
    int m_tile = rl >> 4, rr = rl & 15;
    int c = k >> 5, kin = k & 31;
    int k_tile = kin >> 3, cc = kin & 7;
    int lane = ((rr & 7) << 2) + (cc & 3);
    int reg = ((cc >= 4) ? 2 : 0) + (rr >= 8 ? 1 : 0);
    dst[(size_t)(blk*NCH + c)*4096 + ((m_tile*4 + k_tile)*32 + lane)*4 + reg] = f2tf32(v);
}

// ---------------- conv_B: weights -> permuted tf32 (128-row blocks) --------
__global__ void conv_B(const float* __restrict__ src, uint32_t* __restrict__ dst,
                       int R, int RP){
    int idx = blockIdx.x * blockDim.x + threadIdx.x;
    const int nq = NCH*8;
    if (idx >= RP*nq) return;
    int r = idx / nq, q = idx % nq;
    int k = q << 2;
    float4 v = make_float4(0.f,0.f,0.f,0.f);
    if (r < R && k < HH) v = *(const float4*)(src + (size_t)r*HH + k);
    int blk = r >> 7, rl = r & 127;
    int n_tile = rl >> 3, nn = rl & 7;
    int c = k >> 5, kin = k & 31;
    int k_tile = kin >> 3, cc = kin & 7;
    int reg = (cc >= 4) ? 1 : 0;
    int lane0 = nn << 2;
    size_t base = (size_t)(blk*NCH + c)*4096 + ((n_tile*4 + k_tile)*32 + lane0)*2 + reg;
    dst[base    ] = f2tf32(v.x);
    dst[base + 2] = f2tf32(v.y);
    dst[base + 4] = f2tf32(v.z);
    dst[base + 6] = f2tf32(v.w);
}

// =====================================================================
// GEMM v3: pre-permuted operands, 3-stage cp.async pipeline, 1 sync/chunk.
// Block 128 x TNB, 8 warps (4x2). C[m,n]=sum_k A[m,k]B[n,k] (+bias)
// B buffers are 128-row-blocked; TNB=64 reads half-blocks.
// =====================================================================
template<int TNB, bool BIAS>
__global__ __launch_bounds__(256, 2) void mma_gemm3(
    const uint32_t* __restrict__ Af, const uint32_t* __restrict__ Bf,
    const float* __restrict__ bias, float* __restrict__ C,
    int M, int Nn, int ldc)
{
    constexpr int BS = TNB*32;        // B stage size in u32
    constexpr int NI = TNB/16;        // B frags per warp
    extern __shared__ uint32_t sm3[];
    uint32_t sbase = smem_u32(sm3);
    int tid = threadIdx.x, lane = tid & 31, wid = tid >> 5;
    int wm = wid & 3, wn = wid >> 2;

    const uint32_t* gA = Af + (size_t)blockIdx.y * NCH * 4096;
    const uint32_t* gB;
    if (TNB == 128) gB = Bf + (size_t)blockIdx.x * NCH * 4096;
    else            gB = Bf + (size_t)(blockIdx.x >> 1) * NCH * 4096 + (blockIdx.x & 1) * 2048;

    float d[2][NI][4];
    #pragma unroll
    for (int mi = 0; mi < 2; mi++)
        #pragma unroll
        for (int ni = 0; ni < NI; ni++)
            #pragma unroll
            for (int q = 0; q < 4; q++) d[mi][ni][q] = 0.f;

    auto pre = [&](int c){
        int s = c % 3;
        uint32_t sA = sbase + (uint32_t)s*16384u;
        uint32_t sB = sbase + 49152u + (uint32_t)s*(BS*4);
        const uint32_t* a = gA + c*4096;
        const uint32_t* b = gB + c*4096;   // chunk stride is full 128-block (4096)
        #pragma unroll
        for (int u = 0; u < 4; u++){
            int off = (tid + (u << 8)) << 2;
            cp16(sA + (off << 2), a + off);
        }
        #pragma unroll
        for (int u = 0; u < TNB/32; u++){
            int off = (tid + (u << 8)) << 2;
            cp16(sB + (off << 2), b + off);
        }
        cp_commit();
    };

    pre(0); pre(1);
    for (int c = 0; c < NCH; c++){
        if (c + 1 < NCH) cp_wait<1>(); else cp_wait<0>();
        __syncthreads();
        if (c + 2 < NCH) pre(c + 2);
        const uint32_t* bA = sm3 + (c % 3)*4096;
        const uint32_t* bB = sm3 + 12288 + (c % 3)*BS;
        #pragma unroll
        for (int kt = 0; kt < 4; kt++){
            uint32_t a[2][4], b[NI][2];
            #pragma unroll
            for (int mi = 0; mi < 2; mi++)
                *(uint4*)a[mi] = *(const uint4*)&bA[(((wm*2+mi)*4 + kt)*32 + lane)*4];
            #pragma unroll
            for (int ni = 0; ni < NI; ni++)
                *(uint2*)b[ni] = *(const uint2*)&bB[(((wn*NI+ni)*4 + kt)*32 + lane)*2];
            #pragma unroll
            for (int mi = 0; mi < 2; mi++)
                #pragma unroll
                for (int ni = 0; ni < NI; ni++)
                    mma_tf32(d[mi][ni], a[mi], b[ni]);
        }
    }

    int grp = lane >> 2, qid = lane & 3;
    int tile_m = blockIdx.y * 128, tile_n = blockIdx.x * TNB;
    #pragma unroll
    for (int mi = 0; mi < 2; mi++){
        int row0 = tile_m + wm*32 + mi*16 + grp;
        #pragma unroll
        for (int ni = 0; ni < NI; ni++){
            int col = tile_n + wn*(TNB/2) + ni*8 + qid*2;
            if (col < Nn){
                float b0 = 0.f, b1 = 0.f;
                if (BIAS){ b0 = bias[col]; b1 = bias[col+1]; }
                if (row0 < M){
                    float2 v = make_float2(d[mi][ni][0] + b0, d[mi][ni][1] + b1);
                    *(float2*)(C + (size_t)row0*ldc + col) = v;
                }
                if (row0 + 8 < M){
                    float2 v = make_float2(d[mi][ni][2] + b0, d[mi][ni][3] + b1);
                    *(float2*)(C + (size_t)(row0+8)*ldc + col) = v;
                }
            }
        }
    }
}

#define MG3_SMEM_128 (49152 + 3*128*128)   // 98304
#define MG3_SMEM_64  (49152 + 3*64*128)    // 73728

// ---------------- K1: decoder inputs (+ permuted tf32) ----------------
__global__ void k_decin(const float* __restrict__ emb, const float* __restrict__ slot_emb,
                        const int* __restrict__ dom, const int* __restrict__ slo,
                        const int* __restrict__ tgt){
    int idx = blockIdx.x * blockDim.x + threadIdx.x;
    if (idx >= LL*NN*HH2) return;
    int k = idx % HH2; int r = idx / HH2; int n = r % NN; int l = r / NN;
    float v = 0.f;
    if (k < HH){
        int s = n / BB, b = n % BB;
        if (l == 0) v = slot_emb[dom[s]*HH + k] + slot_emb[slo[s]*HH + k];
        else {
            int tok = tgt[(b*NSLOT + s)*LL + (l-1)];
            v = emb[(size_t)tok*HH + k];
        }
        g_dec_in[(size_t)r*HH + k] = v;
    }
    storeA(cA_dec, r, k, v);
}

// ---------------- K2: init hidden (+ permuted tf32) ----------------
__global__ void k_hinit(const float* __restrict__ enc_hidden){
    int idx = blockIdx.x * blockDim.x + threadIdx.x;
    if (idx >= NN*HH2) return;
    int n = idx / HH2, k = idx % HH2;
    float v = 0.f;
    if (k < HH){
        v = enc_hidden[(n % BB)*HH + k];
        g_hprev[(size_t)n*HH + k] = v;
    }
    storeA(cA_h, n, k, v);
}

// ---------------- K3: GRU gate fuse (+ permuted tf32 for next step & big A) --
__global__ void k_gate(int l){
    int idx = blockIdx.x * blockDim.x + threadIdx.x;
    if (idx >= NN*HH2) return;
    int n = idx / HH2, k = idx % HH2;
    if (k >= HH){
        storeA(cA_h,   n,         k, 0.f);
        storeA(cA_big, n*LL + l,  k, 0.f);
        return;
    }
    const float* gi = g_gi + (size_t)(l*NN + n)*H3;
    const float* gh = g_gh + (size_t)n*H3;
    float r  = sigmoidf(gi[k]        + gh[k]);
    float z  = sigmoidf(gi[HH + k]   + gh[HH + k]);
    float nn = tanhf   (gi[2*HH + k] + r * gh[2*HH + k]);
    float hp = g_hprev[(size_t)n*HH + k];
    float hn = (1.f - z) * nn + z * hp;
    g_h[(size_t)(l*NN + n)*HH + k] = hn;
    g_hprev[(size_t)n*HH + k] = hn;
    storeA(cA_h,   n,        k, hn);
    storeA(cA_big, n*LL + l, k, hn);
}

// ---------------- K4: attention ----------------
#define ENC_PAD 68
__global__ __launch_bounds__(256) void k_attn(const float* __restrict__ enc_out,
                                              const int* __restrict__ lens){
    extern __shared__ float sm[];
    float* sh_h   = sm;
    float* sh_enc = sm + NSLOT*HH;
    float* sh_sc  = sh_enc + TT*ENC_PAD;
    __shared__ float red[8];
    __shared__ float s_mx, s_sum;

    int l  = blockIdx.x / BB;
    int bb = blockIdx.x % BB;
    int tid = threadIdx.x;
    int lane = tid & 31, wrp = tid >> 5;
    int t = tid;

    for (int i = tid; i < NSLOT*HH; i += 256){
        int s = i / HH, h = i % HH;
        sh_h[i] = g_h[(size_t)(l*NN + s*BB + bb)*HH + h];
    }
    for (int i = tid; i < NSLOT*TT; i += 256) sh_sc[i] = 0.f;
    __syncthreads();

    for (int kc = 0; kc < HH; kc += 64){
        int kw = min(64, HH - kc);
        for (int i = tid; i < TT*kw; i += 256){
            int tt2 = i / kw, kk = i % kw;
            sh_enc[tt2*ENC_PAD + kk] = enc_out[((size_t)bb*TT + tt2)*HH + kc + kk];
        }
        __syncthreads();
        for (int sg = 0; sg < NSLOT; sg += 10){
            float acc[10];
            #pragma unroll
            for (int u = 0; u < 10; u++) acc[u] = 0.f;
            for (int kk = 0; kk < kw; kk += 4){
                float4 e = *(const float4*)&sh_enc[t*ENC_PAD + kk];
                #pragma unroll
                for (int u = 0; u < 10; u++){
                    float4 hv = *(const float4*)&sh_h[(sg+u)*HH + kc + kk];
                    acc[u] += hv.x*e.x + hv.y*e.y + hv.z*e.z + hv.w*e.w;
                }
            }
            #pragma unroll
            for (int u = 0; u < 10; u++) sh_sc[(sg+u)*TT + t] += acc[u];
        }
        __syncthreads();
    }

    int len = lens[bb];
    for (int s = 0; s < NSLOT; s++){
        float v = (t < len) ? sh_sc[s*TT + t] : -1e9f;
        float m = warpMax(v);
        if (lane == 0) red[wrp] = m;
        __syncthreads();
        if (tid == 0){
            float mm = red[0];
            #pragma unroll
            for (int i = 1; i < 8; i++) mm = fmaxf(mm, red[i]);
            s_mx = mm;
        }
        __syncthreads();
        float p = expf(v - s_mx);
        float su = warpSum(p);
        if (lane == 0) red[wrp] = su;
        __syncthreads();
        if (tid == 0){
            float ss = 0.f;
            #pragma unroll
            for (int i = 0; i < 8; i++) ss += red[i];
            s_sum = ss;
        }
        __syncthreads();
        p /= s_sum;
        sh_sc[s*TT + t] = p;
        g_prob[(size_t)(l*NN + s*BB + bb)*TT + t] = p;
        __syncthreads();
    }

    for (int hc = 0; hc < HH; hc += 64){
        int hw = min(64, HH - hc);
        __syncthreads();
        for (int i = tid; i < TT*hw; i += 256){
            int tt2 = i / hw, hh = i % hw;
            sh_enc[tt2*ENC_PAD + hh] = enc_out[((size_t)bb*TT + tt2)*HH + hc + hh];
        }
        __syncthreads();
        int nq = NSLOT * (hw >> 2);
        for (int oi = tid; oi < nq; oi += 256){
            int s  = oi / (hw >> 2);
            int h4 = (oi % (hw >> 2)) * 4;
            float4 a = make_float4(0,0,0,0);
            for (int tt2 = 0; tt2 < TT; tt2++){
                float p = sh_sc[s*TT + tt2];
                float4 e = *(const float4*)&sh_enc[tt2*ENC_PAD + h4];
                a.x += p*e.x; a.y += p*e.y; a.z += p*e.z; a.w += p*e.w;
            }
            *(float4*)&g_ctx[(size_t)(l*NN + s*BB + bb)*HH + hc + h4] = a;
        }
    }
}

// ---------------- K5: switch ----------------
__global__ void k_switch(const float* __restrict__ w_ratio, const float* __restrict__ b_ratio){
    int row = blockIdx.x;
    int tid = threadIdx.x;
    const float* h = g_h      + (size_t)row*HH;
    const float* c = g_ctx    + (size_t)row*HH;
    const float* x = g_dec_in + (size_t)row*HH;
    float a = 0.f;
    for (int i = tid; i < HH; i += 128)
        a += h[i]*w_ratio[i] + c[i]*w_ratio[HH + i] + x[i]*w_ratio[2*HH + i];
    __shared__ float red[4];
    a = warpSum(a);
    if ((tid & 31) == 0) red[tid >> 5] = a;
    __syncthreads();
    if (tid == 0){
        float tot = red[0] + red[1] + red[2] + red[3] + b_ratio[0];
        g_switch[row] = sigmoidf(tot);
    }
}

// ---------------- K6: gates head ----------------
__global__ void k_gates(const float* __restrict__ w_gate, const float* __restrict__ b_gate,
                        float* __restrict__ out_gates){
    int n = blockIdx.x;
    int tid = threadIdx.x;
    const float* c = g_ctx + (size_t)n*HH;
    float a0 = 0.f, a1 = 0.f, a2 = 0.f;
    for (int i = tid; i < HH; i += 128){
        float cv = c[i];
        a0 += cv * w_gate[i];
        a1 += cv * w_gate[HH + i];
        a2 += cv * w_gate[2*HH + i];
    }
    __shared__ float red[3][4];
    a0 = warpSum(a0); a1 = warpSum(a1); a2 = warpSum(a2);
    if ((tid & 31) == 0){
        int w = tid >> 5;
        red[0][w] = a0; red[1][w] = a1; red[2][w] = a2;
    }
    __syncthreads();
    if (tid < GG){
        float tot = red[tid][0] + red[tid][1] + red[tid][2] + red[tid][3] + b_gate[tid];
        out_gates[(size_t)n*GG + tid] = tot;
    }
}

// ---------------- K8: softmax + pointer scatter + mix ----------------
__global__ __launch_bounds__(256) void k_softmix(float* __restrict__ out,
                                                 const int* __restrict__ story){
    extern __shared__ float smx[];
    float* pctx = smx;
    float* vals = smx + VV;
    __shared__ float red[8];
    __shared__ float s_mx, s_sum;
    int m = blockIdx.x, tid = threadIdx.x;
    int lane = tid & 31, wrp = tid >> 5;
    int n = m / LL, l = m % LL, bb = n % BB;
    int rowa = l*NN + n;
    float sw = g_switch[rowa];

    for (int i = tid; i < VV; i += 256) pctx[i] = 0.f;
    float* base = out + (size_t)m*VV;
    float lm = -INFINITY;
    for (int v = tid; v < VV; v += 256){
        float x = base[v];
        vals[v] = x;
        lm = fmaxf(lm, x);
    }
    __syncthreads();
    {
        float p = g_prob[(size_t)rowa*TT + tid];
        int c = story[bb*TT + tid];
        atomicAdd(&pctx[c], p);
    }
    lm = warpMax(lm);
    if (lane == 0) red[wrp] = lm;
    __syncthreads();
    if (tid == 0){
        float mm = red[0];
        #pragma unroll
        for (int i = 1; i < 8; i++) mm = fmaxf(mm, red[i]);
        s_mx = mm;
    }
    __syncthreads();
    float mx = s_mx;
    float ls = 0.f;
    for (int v = tid; v < VV; v += 256){
        float e = expf(vals[v] - mx);
        vals[v] = e;
        ls += e;
    }
    ls = warpSum(ls);
    if (lane == 0) red[wrp] = ls;
    __syncthreads();
    if (tid == 0){
        float ss = 0.f;
        #pragma unroll
        for (int i = 0; i < 8; i++) ss += red[i];
        s_sum = ss;
    }
    __syncthreads();
    float scale = sw / s_sum;
    float osw = 1.f - sw;
    for (int v = tid; v < VV; v += 256)
        base[v] = vals[v] * scale + osw * pctx[v];
}

// ---------------- launch ----------------
extern "C" void kernel_launch(void* const* d_in, const int* in_sizes, int n_in,
                              void* d_out, int out_size){
    const float* enc_hidden = (const float*)d_in[0];
    const float* enc_out    = (const float*)d_in[1];
    const float* emb        = (const float*)d_in[2];
    const float* w_ih       = (const float*)d_in[3];
    const float* w_hh       = (const float*)d_in[4];
    const float* b_ih       = (const float*)d_in[5];
    const float* b_hh       = (const float*)d_in[6];
    const float* w_ratio    = (const float*)d_in[7];
    const float* b_ratio    = (const float*)d_in[8];
    const float* w_gate     = (const float*)d_in[9];
    const float* b_gate     = (const float*)d_in[10];
    const float* slot_emb   = (const float*)d_in[11];
    const int*   lens       = (const int*)d_in[12];
    const int*   story      = (const int*)d_in[13];
    const int*   tgt        = (const int*)d_in[14];
    const int*   dom        = (const int*)d_in[15];
    const int*   slo        = (const int*)d_in[16];
    float* out = (float*)d_out;

    float *p_gi, *p_gh;
    uint32_t *pA_dec, *pA_big, *pA_h, *pB_emb, *pB_wih, *pB_whh;
    cudaGetSymbolAddress((void**)&p_gi,    g_gi);
    cudaGetSymbolAddress((void**)&p_gh,    g_gh);
    cudaGetSymbolAddress((void**)&pA_dec,  cA_dec);
    cudaGetSymbolAddress((void**)&pA_big,  cA_big);
    cudaGetSymbolAddress((void**)&pA_h,    cA_h);
    cudaGetSymbolAddress((void**)&pB_emb,  cB_emb);
    cudaGetSymbolAddress((void**)&pB_wih,  cB_wih);
    cudaGetSymbolAddress((void**)&pB_whh,  cB_whh);

    const int ATTN_SMEM = (NSLOT*HH + TT*ENC_PAD + NSLOT*TT) * 4;
    const int SMX_SMEM  = 2*VV*4;
    cudaFuncSetAttribute(k_attn, cudaFuncAttributeMaxDynamicSharedMemorySize, ATTN_SMEM);
    cudaFuncSetAttribute(k_softmix, cudaFuncAttributeMaxDynamicSharedMemorySize, SMX_SMEM);
    cudaFuncSetAttribute((const void*)mma_gemm3<128,true>,  cudaFuncAttributeMaxDynamicSharedMemorySize, MG3_SMEM_128);
    cudaFuncSetAttribute((const void*)mma_gemm3<128,false>, cudaFuncAttributeMaxDynamicSharedMemorySize, MG3_SMEM_128);
    cudaFuncSetAttribute((const void*)mma_gemm3<64,true>,   cudaFuncAttributeMaxDynamicSharedMemorySize, MG3_SMEM_64);

    const int nq = NCH*8;

    // 0) weight conversions
    conv_B<<<(NBN_EMB*128*nq + 255)/256, 256>>>(emb,  pB_emb, VV,  NBN_EMB*128);
    conv_B<<<(NBN_W  *128*nq + 255)/256, 256>>>(w_ih, pB_wih, H3,  NBN_W*128);
    conv_B<<<(NBN_W  *128*nq + 255)/256, 256>>>(w_hh, pB_whh, H3,  NBN_W*128);

    // 1) decoder inputs + h0 (fused permuted-A writes)
    k_decin<<<(LL*NN*HH2 + 255)/256, 256>>>(emb, slot_emb, dom, slo, tgt);
    k_hinit<<<(NN*HH2 + 255)/256, 256>>>(enc_hidden);

    // 2) input-side gates, all steps
    {
        dim3 grid(NBN_W, NBM_BIG);
        mma_gemm3<128,true><<<grid, 256, MG3_SMEM_128>>>(pA_dec, pB_wih, b_ih, p_gi, MM, H3, H3);
    }

    // 3) GRU recurrence (TN=64 -> 76 blocks; conv fused into k_gate/k_hinit)
    for (int l = 0; l < LL; l++){
        dim3 grid((H3 + 63)/64, NBM_H);
        mma_gemm3<64,true><<<grid, 256, MG3_SMEM_64>>>(pA_h, pB_whh, b_hh, p_gh, NN, H3, H3);
        k_gate<<<(NN*HH2 + 255)/256, 256>>>(l);
    }

    // 4) attention
    k_attn<<<LL*BB, 256, ATTN_SMEM>>>(enc_out, lens);

    // 5) switch; 6) gates head
    k_switch<<<LL*NN, 128>>>(w_ratio, b_ratio);
    k_gates<<<NN, 128>>>(w_gate, b_gate, out + POINTS_ELEMS);

    // 7) big vocab GEMM (A already permuted by k_gate), logits into d_out
    {
        dim3 grid(NBN_EMB, NBM_BIG);
        mma_gemm3<128,false><<<grid, 256, MG3_SMEM_128>>>(pA_big, pB_emb, nullptr, out, MM, VV, VV);
    }

    // 8) softmax + pointer scatter + mix, in place
    k_softmix<<<MM, 256, SMX_SMEM>>>(out, story);
}

// round 6
// speedup vs baseline: 1.4680x; 1.4680x over previous
#include <cuda_runtime.h>
#include <cstdint>
#include <math.h>

// ---------------- problem constants ----------------
#define BB 16
#define TT 256
#define VV 18000
#define NSLOT 30
#define LL 10
#define GG 3
#define HH 400
#define HH2 416           // K padded to NCH*32
#define NN (NSLOT*BB)     // 480
#define MM (LL*NN)        // 4800
#define H3 (3*HH)         // 1200
#define NCH 13

#define NBM_BIG 38        // ceil(4800/128)
#define NBM_H   4         // ceil(480/128)
#define NBN_EMB 141       // ceil(18000/128)
#define NBN_W   10        // ceil(1200/128)

static const size_t POINTS_ELEMS = (size_t)MM * VV;

// ---------------- scratch ----------------
__device__ __align__(128) float g_dec_in[LL*NN*HH];
__device__ __align__(128) float g_gi[LL*NN*H3];
__device__ __align__(128) float g_h[LL*NN*HH];
__device__ __align__(128) float g_hprev[NN*HH];
__device__ __align__(128) float g_gh[NN*H3];
__device__ __align__(128) float g_prob[LL*NN*TT];
__device__ __align__(128) float g_ctx[LL*NN*HH];
__device__ __align__(128) float g_switch[LL*NN];

// fragment-permuted tf32 operand buffers (zero-init at load; pads rewritten each run)
__device__ __align__(128) uint32_t cA_dec[NBM_BIG*NCH*4096];
__device__ __align__(128) uint32_t cA_big[NBM_BIG*NCH*4096];
__device__ __align__(128) uint32_t cA_h  [NBM_H  *NCH*4096];
__device__ __align__(128) uint32_t cB_emb[NBN_EMB*NCH*4096];
__device__ __align__(128) uint32_t cB_wih[NBN_W  *NCH*4096];
__device__ __align__(128) uint32_t cB_whh[NBN_W  *NCH*4096];

// ---------------- helpers ----------------
__device__ __forceinline__ float warpMax(float v){
    #pragma unroll
    for (int o = 16; o; o >>= 1) v = fmaxf(v, __shfl_xor_sync(0xffffffffu, v, o));
    return v;
}
__device__ __forceinline__ float warpSum(float v){
    #pragma unroll
    for (int o = 16; o; o >>= 1) v += __shfl_xor_sync(0xffffffffu, v, o);
    return v;
}
__device__ __forceinline__ float sigmoidf(float x){ return 1.f / (1.f + expf(-x)); }
__device__ __forceinline__ uint32_t f2tf32(float x){
    uint32_t r;
    asm("cvt.rna.tf32.f32 %0, %1;" : "=r"(r) : "f"(x));
    return r;
}
__device__ __forceinline__ void mma_tf32(float* d, const uint32_t* a, const uint32_t* b){
    asm volatile(
        "mma.sync.aligned.m16n8k8.row.col.f32.tf32.tf32.f32 "
        "{%0,%1,%2,%3}, {%4,%5,%6,%7}, {%8,%9}, {%0,%1,%2,%3};\n"
        : "+f"(d[0]), "+f"(d[1]), "+f"(d[2]), "+f"(d[3])
        : "r"(a[0]), "r"(a[1]), "r"(a[2]), "r"(a[3]), "r"(b[0]), "r"(b[1]));
}
__device__ __forceinline__ uint32_t smem_u32(const void* p){
    uint32_t a;
    asm("{ .reg .u64 t; cvta.to.shared.u64 t, %1; cvt.u32.u64 %0, t; }" : "=r"(a) : "l"(p));
    return a;
}
__device__ __forceinline__ void cp16(uint32_t saddr, const void* g){
    asm volatile("cp.async.ca.shared.global [%0], [%1], 16;" :: "r"(saddr), "l"(g) : "memory");
}
__device__ __forceinline__ void cp_commit(){ asm volatile("cp.async.commit_group;" ::: "memory"); }
template<int W> __device__ __forceinline__ void cp_wait(){
    asm volatile("cp.async.wait_group %0;" :: "n"(W) : "memory");
}

// permuted single-element store into A-fragment buffer (128-row blocks)
__device__ __forceinline__ void storeA(uint32_t* dst, int r, int k, float v){
    int blk = r >> 7, rl = r & 127;
    int m_tile = rl >> 4, rr = rl & 15;
    int c = k >> 5, kin = k & 31;
    int k_tile = kin >> 3, cc = kin & 7;
    int lane = ((rr & 7) << 2) + (cc & 3);
    int reg = ((cc >= 4) ? 2 : 0) + (rr >= 8 ? 1 : 0);
    dst[(size_t)(blk*NCH + c)*4096 + ((m_tile*4 + k_tile)*32 + lane)*4 + reg] = f2tf32(v);
}

// ---------------- conv_B: weights -> permuted tf32 (128-row blocks) --------
__global__ void conv_B(const float* __restrict__ src, uint32_t* __restrict__ dst,
                       int R, int RP){
    int idx = blockIdx.x * blockDim.x + threadIdx.x;
    const int nq = NCH*8;
    if (idx >= RP*nq) return;
    int r = idx / nq, q = idx % nq;
    int k = q << 2;
    float4 v = make_float4(0.f,0.f,0.f,0.f);
    if (r < R && k < HH) v = *(const float4*)(src + (size_t)r*HH + k);
    int blk = r >> 7, rl = r & 127;
    int n_tile = rl >> 3, nn = rl & 7;
    int c = k >> 5, kin = k & 31;
    int k_tile = kin >> 3, cc = kin & 7;
    int reg = (cc >= 4) ? 1 : 0;
    int lane0 = nn << 2;
    size_t base = (size_t)(blk*NCH + c)*4096 + ((n_tile*4 + k_tile)*32 + lane0)*2 + reg;
    dst[base    ] = f2tf32(v.x);
    dst[base + 2] = f2tf32(v.y);
    dst[base + 4] = f2tf32(v.z);
    dst[base + 6] = f2tf32(v.w);
}

// =====================================================================
// GEMM (R4-proven config): pre-permuted operands, 2-stage cp.async,
// two syncs per chunk, NO min-blocks clause. Block 128 x TNB, 8 warps 4x2.
// =====================================================================
template<int TNB, bool BIAS>
__global__ __launch_bounds__(256) void mma_gemm2(
    const uint32_t* __restrict__ Af, const uint32_t* __restrict__ Bf,
    const float* __restrict__ bias, float* __restrict__ C,
    int M, int Nn, int ldc)
{
    constexpr int BS = TNB*32;        // B stage size in u32
    constexpr int NI = TNB/16;        // B frags per warp
    extern __shared__ uint32_t sm2[];
    uint32_t sbase = smem_u32(sm2);
    int tid = threadIdx.x, lane = tid & 31, wid = tid >> 5;
    int wm = wid & 3, wn = wid >> 2;

    const uint32_t* gA = Af + (size_t)blockIdx.y * NCH * 4096;
    const uint32_t* gB;
    if (TNB == 128) gB = Bf + (size_t)blockIdx.x * NCH * 4096;
    else            gB = Bf + (size_t)(blockIdx.x >> 1) * NCH * 4096 + (blockIdx.x & 1) * 2048;

    float d[2][NI][4];
    #pragma unroll
    for (int mi = 0; mi < 2; mi++)
        #pragma unroll
        for (int ni = 0; ni < NI; ni++)
            #pragma unroll
            for (int q = 0; q < 4; q++) d[mi][ni][q] = 0.f;

    auto pre = [&](int c){
        int s = c & 1;
        uint32_t sA = sbase + (uint32_t)s*16384u;
        uint32_t sB = sbase + 32768u + (uint32_t)s*(BS*4);
        const uint32_t* a = gA + c*4096;
        const uint32_t* b = gB + c*4096;
        #pragma unroll
        for (int u = 0; u < 4; u++){
            int off = (tid + (u << 8)) << 2;
            cp16(sA + (off << 2), a + off);
        }
        #pragma unroll
        for (int u = 0; u < TNB/32; u++){
            int off = (tid + (u << 8)) << 2;
            cp16(sB + (off << 2), b + off);
        }
        cp_commit();
    };

    pre(0);
    for (int c = 0; c < NCH; c++){
        if (c + 1 < NCH){ pre(c + 1); cp_wait<1>(); }
        else cp_wait<0>();
        __syncthreads();
        const uint32_t* bA = sm2 + (c & 1)*4096;
        const uint32_t* bB = sm2 + 8192 + (c & 1)*BS;
        #pragma unroll
        for (int kt = 0; kt < 4; kt++){
            uint32_t a[2][4], b[NI][2];
            #pragma unroll
            for (int mi = 0; mi < 2; mi++)
                *(uint4*)a[mi] = *(const uint4*)&bA[(((wm*2+mi)*4 + kt)*32 + lane)*4];
            #pragma unroll
            for (int ni = 0; ni < NI; ni++)
                *(uint2*)b[ni] = *(const uint2*)&bB[(((wn*NI+ni)*4 + kt)*32 + lane)*2];
            #pragma unroll
            for (int mi = 0; mi < 2; mi++)
                #pragma unroll
                for (int ni = 0; ni < NI; ni++)
                    mma_tf32(d[mi][ni], a[mi], b[ni]);
        }
        __syncthreads();
    }

    int grp = lane >> 2, qid = lane & 3;
    int tile_m = blockIdx.y * 128, tile_n = blockIdx.x * TNB;
    #pragma unroll
    for (int mi = 0; mi < 2; mi++){
        int row0 = tile_m + wm*32 + mi*16 + grp;
        #pragma unroll
        for (int ni = 0; ni < NI; ni++){
            int col = tile_n + wn*(TNB/2) + ni*8 + qid*2;
            if (col < Nn){
                float b0 = 0.f, b1 = 0.f;
                if (BIAS){ b0 = bias[col]; b1 = bias[col+1]; }
                if (row0 < M){
                    float2 v = make_float2(d[mi][ni][0] + b0, d[mi][ni][1] + b1);
                    *(float2*)(C + (size_t)row0*ldc + col) = v;
                }
                if (row0 + 8 < M){
                    float2 v = make_float2(d[mi][ni][2] + b0, d[mi][ni][3] + b1);
                    *(float2*)(C + (size_t)(row0+8)*ldc + col) = v;
                }
            }
        }
    }
}

#define MG2_SMEM_128 (2*(4096+4096)*4)   // 65536
#define MG2_SMEM_64  (2*(4096+2048)*4)   // 49152

// ---------------- K1: decoder inputs (+ fused permuted tf32) ----------------
__global__ void k_decin(const float* __restrict__ emb, const float* __restrict__ slot_emb,
                        const int* __restrict__ dom, const int* __restrict__ slo,
                        const int* __restrict__ tgt){
    int idx = blockIdx.x * blockDim.x + threadIdx.x;
    if (idx >= LL*NN*HH2) return;
    int k = idx % HH2; int r = idx / HH2; int n = r % NN; int l = r / NN;
    float v = 0.f;
    if (k < HH){
        int s = n / BB, b = n % BB;
        if (l == 0) v = slot_emb[dom[s]*HH + k] + slot_emb[slo[s]*HH + k];
        else {
            int tok = tgt[(b*NSLOT + s)*LL + (l-1)];
            v = emb[(size_t)tok*HH + k];
        }
        g_dec_in[(size_t)r*HH + k] = v;
    }
    storeA(cA_dec, r, k, v);
}

// ---------------- K2: init hidden (+ fused permuted tf32) ----------------
__global__ void k_hinit(const float* __restrict__ enc_hidden){
    int idx = blockIdx.x * blockDim.x + threadIdx.x;
    if (idx >= NN*HH2) return;
    int n = idx / HH2, k = idx % HH2;
    float v = 0.f;
    if (k < HH){
        v = enc_hidden[(n % BB)*HH + k];
        g_hprev[(size_t)n*HH + k] = v;
    }
    storeA(cA_h, n, k, v);
}

// ---------------- K3: GRU gate fuse (+ fused permuted tf32) ----------------
__global__ void k_gate(int l){
    int idx = blockIdx.x * blockDim.x + threadIdx.x;
    if (idx >= NN*HH2) return;
    int n = idx / HH2, k = idx % HH2;
    if (k >= HH){
        storeA(cA_h,   n,         k, 0.f);
        storeA(cA_big, n*LL + l,  k, 0.f);
        return;
    }
    const float* gi = g_gi + (size_t)(l*NN + n)*H3;
    const float* gh = g_gh + (size_t)n*H3;
    float r  = sigmoidf(gi[k]        + gh[k]);
    float z  = sigmoidf(gi[HH + k]   + gh[HH + k]);
    float nn = tanhf   (gi[2*HH + k] + r * gh[2*HH + k]);
    float hp = g_hprev[(size_t)n*HH + k];
    float hn = (1.f - z) * nn + z * hp;
    g_h[(size_t)(l*NN + n)*HH + k] = hn;
    g_hprev[(size_t)n*HH + k] = hn;
    storeA(cA_h,   n,        k, hn);
    storeA(cA_big, n*LL + l, k, hn);
}

// ---------------- K4: attention ----------------
#define ENC_PAD 68
__global__ __launch_bounds__(256) void k_attn(const float* __restrict__ enc_out,
                                              const int* __restrict__ lens){
    extern __shared__ float sm[];
    float* sh_h   = sm;
    float* sh_enc = sm + NSLOT*HH;
    float* sh_sc  = sh_enc + TT*ENC_PAD;
    __shared__ float red[8];
    __shared__ float s_mx, s_sum;

    int l  = blockIdx.x / BB;
    int bb = blockIdx.x % BB;
    int tid = threadIdx.x;
    int lane = tid & 31, wrp = tid >> 5;
    int t = tid;

    for (int i = tid; i < NSLOT*HH; i += 256){
        int s = i / HH, h = i % HH;
        sh_h[i] = g_h[(size_t)(l*NN + s*BB + bb)*HH + h];
    }
    for (int i = tid; i < NSLOT*TT; i += 256) sh_sc[i] = 0.f;
    __syncthreads();

    for (int kc = 0; kc < HH; kc += 64){
        int kw = min(64, HH - kc);
        for (int i = tid; i < TT*kw; i += 256){
            int tt2 = i / kw, kk = i % kw;
            sh_enc[tt2*ENC_PAD + kk] = enc_out[((size_t)bb*TT + tt2)*HH + kc + kk];
        }
        __syncthreads();
        for (int sg = 0; sg < NSLOT; sg += 10){
            float acc[10];
            #pragma unroll
            for (int u = 0; u < 10; u++) acc[u] = 0.f;
            for (int kk = 0; kk < kw; kk += 4){
                float4 e = *(const float4*)&sh_enc[t*ENC_PAD + kk];
                #pragma unroll
                for (int u = 0; u < 10; u++){
                    float4 hv = *(const float4*)&sh_h[(sg+u)*HH + kc + kk];
                    acc[u] += hv.x*e.x + hv.y*e.y + hv.z*e.z + hv.w*e.w;
                }
            }
            #pragma unroll
            for (int u = 0; u < 10; u++) sh_sc[(sg+u)*TT + t] += acc[u];
        }
        __syncthreads();
    }

    int len = lens[bb];
    for (int s = 0; s < NSLOT; s++){
        float v = (t < len) ? sh_sc[s*TT + t] : -1e9f;
        float m = warpMax(v);
        if (lane == 0) red[wrp] = m;
        __syncthreads();
        if (tid == 0){
            float mm = red[0];
            #pragma unroll
            for (int i = 1; i < 8; i++) mm = fmaxf(mm, red[i]);
            s_mx = mm;
        }
        __syncthreads();
        float p = expf(v - s_mx);
        float su = warpSum(p);
        if (lane == 0) red[wrp] = su;
        __syncthreads();
        if (tid == 0){
            float ss = 0.f;
            #pragma unroll
            for (int i = 0; i < 8; i++) ss += red[i];
            s_sum = ss;
        }
        __syncthreads();
        p /= s_sum;
        sh_sc[s*TT + t] = p;
        g_prob[(size_t)(l*NN + s*BB + bb)*TT + t] = p;
        __syncthreads();
    }

    for (int hc = 0; hc < HH; hc += 64){
        int hw = min(64, HH - hc);
        __syncthreads();
        for (int i = tid; i < TT*hw; i += 256){
            int tt2 = i / hw, hh = i % hw;
            sh_enc[tt2*ENC_PAD + hh] = enc_out[((size_t)bb*TT + tt2)*HH + hc + hh];
        }
        __syncthreads();
        int nq = NSLOT * (hw >> 2);
        for (int oi = tid; oi < nq; oi += 256){
            int s  = oi / (hw >> 2);
            int h4 = (oi % (hw >> 2)) * 4;
            float4 a = make_float4(0,0,0,0);
            for (int tt2 = 0; tt2 < TT; tt2++){
                float p = sh_sc[s*TT + tt2];
                float4 e = *(const float4*)&sh_enc[tt2*ENC_PAD + h4];
                a.x += p*e.x; a.y += p*e.y; a.z += p*e.z; a.w += p*e.w;
            }
            *(float4*)&g_ctx[(size_t)(l*NN + s*BB + bb)*HH + hc + h4] = a;
        }
    }
}

// ---------------- K5: switch ----------------
__global__ void k_switch(const float* __restrict__ w_ratio, const float* __restrict__ b_ratio){
    int row = blockIdx.x;
    int tid = threadIdx.x;
    const float* h = g_h      + (size_t)row*HH;
    const float* c = g_ctx    + (size_t)row*HH;
    const float* x = g_dec_in + (size_t)row*HH;
    float a = 0.f;
    for (int i = tid; i < HH; i += 128)
        a += h[i]*w_ratio[i] + c[i]*w_ratio[HH + i] + x[i]*w_ratio[2*HH + i];
    __shared__ float red[4];
    a = warpSum(a);
    if ((tid & 31) == 0) red[tid >> 5] = a;
    __syncthreads();
    if (tid == 0){
        float tot = red[0] + red[1] + red[2] + red[3] + b_ratio[0];
        g_switch[row] = sigmoidf(tot);
    }
}

// ---------------- K6: gates head ----------------
__global__ void k_gates(const float* __restrict__ w_gate, const float* __restrict__ b_gate,
                        float* __restrict__ out_gates){
    int n = blockIdx.x;
    int tid = threadIdx.x;
    const float* c = g_ctx + (size_t)n*HH;
    float a0 = 0.f, a1 = 0.f, a2 = 0.f;
    for (int i = tid; i < HH; i += 128){
        float cv = c[i];
        a0 += cv * w_gate[i];
        a1 += cv * w_gate[HH + i];
        a2 += cv * w_gate[2*HH + i];
    }
    __shared__ float red[3][4];
    a0 = warpSum(a0); a1 = warpSum(a1); a2 = warpSum(a2);
    if ((tid & 31) == 0){
        int w = tid >> 5;
        red[0][w] = a0; red[1][w] = a1; red[2][w] = a2;
    }
    __syncthreads();
    if (tid < GG){
        float tot = red[tid][0] + red[tid][1] + red[tid][2] + red[tid][3] + b_gate[tid];
        out_gates[(size_t)n*GG + tid] = tot;
    }
}

// ---------------- K8: softmax + pointer scatter + mix ----------------
__global__ __launch_bounds__(256) void k_softmix(float* __restrict__ out,
                                                 const int* __restrict__ story){
    extern __shared__ float smx[];
    float* pctx = smx;
    float* vals = smx + VV;
    __shared__ float red[8];
    __shared__ float s_mx, s_sum;
    int m = blockIdx.x, tid = threadIdx.x;
    int lane = tid & 31, wrp = tid >> 5;
    int n = m / LL, l = m % LL, bb = n % BB;
    int rowa = l*NN + n;
    float sw = g_switch[rowa];

    for (int i = tid; i < VV; i += 256) pctx[i] = 0.f;
    float* base = out + (size_t)m*VV;
    float lm = -INFINITY;
    for (int v = tid; v < VV; v += 256){
        float x = base[v];
        vals[v] = x;
        lm = fmaxf(lm, x);
    }
    __syncthreads();
    {
        float p = g_prob[(size_t)rowa*TT + tid];
        int c = story[bb*TT + tid];
        atomicAdd(&pctx[c], p);
    }
    lm = warpMax(lm);
    if (lane == 0) red[wrp] = lm;
    __syncthreads();
    if (tid == 0){
        float mm = red[0];
        #pragma unroll
        for (int i = 1; i < 8; i++) mm = fmaxf(mm, red[i]);
        s_mx = mm;
    }
    __syncthreads();
    float mx = s_mx;
    float ls = 0.f;
    for (int v = tid; v < VV; v += 256){
        float e = expf(vals[v] - mx);
        vals[v] = e;
        ls += e;
    }
    ls = warpSum(ls);
    if (lane == 0) red[wrp] = ls;
    __syncthreads();
    if (tid == 0){
        float ss = 0.f;
        #pragma unroll
        for (int i = 0; i < 8; i++) ss += red[i];
        s_sum = ss;
    }
    __syncthreads();
    float scale = sw / s_sum;
    float osw = 1.f - sw;
    for (int v = tid; v < VV; v += 256)
        base[v] = vals[v] * scale + osw * pctx[v];
}

// ---------------- launch ----------------
extern "C" void kernel_launch(void* const* d_in, const int* in_sizes, int n_in,
                              void* d_out, int out_size){
    const float* enc_hidden = (const float*)d_in[0];
    const float* enc_out    = (const float*)d_in[1];
    const float* emb        = (const float*)d_in[2];
    const float* w_ih       = (const float*)d_in[3];
    const float* w_hh       = (const float*)d_in[4];
    const float* b_ih       = (const float*)d_in[5];
    const float* b_hh       = (const float*)d_in[6];
    const float* w_ratio    = (const float*)d_in[7];
    const float* b_ratio    = (const float*)d_in[8];
    const float* w_gate     = (const float*)d_in[9];
    const float* b_gate     = (const float*)d_in[10];
    const float* slot_emb   = (const float*)d_in[11];
    const int*   lens       = (const int*)d_in[12];
    const int*   story      = (const int*)d_in[13];
    const int*   tgt        = (const int*)d_in[14];
    const int*   dom        = (const int*)d_in[15];
    const int*   slo        = (const int*)d_in[16];
    float* out = (float*)d_out;

    float *p_gi, *p_gh;
    uint32_t *pA_dec, *pA_big, *pA_h, *pB_emb, *pB_wih, *pB_whh;
    cudaGetSymbolAddress((void**)&p_gi,    g_gi);
    cudaGetSymbolAddress((void**)&p_gh,    g_gh);
    cudaGetSymbolAddress((void**)&pA_dec,  cA_dec);
    cudaGetSymbolAddress((void**)&pA_big,  cA_big);
    cudaGetSymbolAddress((void**)&pA_h,    cA_h);
    cudaGetSymbolAddress((void**)&pB_emb,  cB_emb);
    cudaGetSymbolAddress((void**)&pB_wih,  cB_wih);
    cudaGetSymbolAddress((void**)&pB_whh,  cB_whh);

    const int ATTN_SMEM = (NSLOT*HH + TT*ENC_PAD + NSLOT*TT) * 4;
    const int SMX_SMEM  = 2*VV*4;
    cudaFuncSetAttribute(k_attn, cudaFuncAttributeMaxDynamicSharedMemorySize, ATTN_SMEM);
    cudaFuncSetAttribute(k_softmix, cudaFuncAttributeMaxDynamicSharedMemorySize, SMX_SMEM);
    cudaFuncSetAttribute((const void*)mma_gemm2<128,true>,  cudaFuncAttributeMaxDynamicSharedMemorySize, MG2_SMEM_128);
    cudaFuncSetAttribute((const void*)mma_gemm2<128,false>, cudaFuncAttributeMaxDynamicSharedMemorySize, MG2_SMEM_128);
    cudaFuncSetAttribute((const void*)mma_gemm2<64,true>,   cudaFuncAttributeMaxDynamicSharedMemorySize, MG2_SMEM_64);

    const int nq = NCH*8;

    // 0) weight conversions
    conv_B<<<(NBN_EMB*128*nq + 255)/256, 256>>>(emb,  pB_emb, VV,  NBN_EMB*128);
    conv_B<<<(NBN_W  *128*nq + 255)/256, 256>>>(w_ih, pB_wih, H3,  NBN_W*128);
    conv_B<<<(NBN_W  *128*nq + 255)/256, 256>>>(w_hh, pB_whh, H3,  NBN_W*128);

    // 1) decoder inputs + h0 (fused permuted-A writes)
    k_decin<<<(LL*NN*HH2 + 255)/256, 256>>>(emb, slot_emb, dom, slo, tgt);
    k_hinit<<<(NN*HH2 + 255)/256, 256>>>(enc_hidden);

    // 2) input-side gates, all steps
    {
        dim3 grid(NBN_W, NBM_BIG);
        mma_gemm2<128,true><<<grid, 256, MG2_SMEM_128>>>(pA_dec, pB_wih, b_ih, p_gi, MM, H3, H3);
    }

    // 3) GRU recurrence (TN=64 -> 76 blocks; conversions fused in k_gate/k_hinit)
    for (int l = 0; l < LL; l++){
        dim3 grid((H3 + 63)/64, NBM_H);
        mma_gemm2<64,true><<<grid, 256, MG2_SMEM_64>>>(pA_h, pB_whh, b_hh, p_gh, NN, H3, H3);
        k_gate<<<(NN*HH2 + 255)/256, 256>>>(l);
    }

    // 4) attention
    k_attn<<<LL*BB, 256, ATTN_SMEM>>>(enc_out, lens);

    // 5) switch; 6) gates head
    k_switch<<<LL*NN, 128>>>(w_ratio, b_ratio);
    k_gates<<<NN, 128>>>(w_gate, b_gate, out + POINTS_ELEMS);

    // 7) big vocab GEMM (A already permuted by k_gate), logits into d_out
    {
        dim3 grid(NBN_EMB, NBM_BIG);
        mma_gemm2<128,false><<<grid, 256, MG2_SMEM_128>>>(pA_big, pB_emb, nullptr, out, MM, VV, VV);
    }

    // 8) softmax + pointer scatter + mix, in place
    k_softmix<<<MM, 256, SMX_SMEM>>>(out, story);
}

// round 7
// speedup vs baseline: 1.6736x; 1.1401x over previous
#include <cuda_runtime.h>
#include <cuda_fp16.h>
#include <cstdint>
#include <math.h>

// ---------------- problem constants ----------------
#define BB 16
#define TT 256
#define VV 18000
#define NSLOT 30
#define LL 10
#define GG 3
#define HH 400
#define HH2 416           // K padded to NCH*32
#define NN (NSLOT*BB)     // 480
#define MM (LL*NN)        // 4800
#define H3 (3*HH)         // 1200
#define NCH 13

#define NBM_BIG 38        // ceil(4800/128)
#define NBM_H   4
#define NBN_EMB 141       // ceil(18000/128)
#define NBN_W   10        // ceil(1200/128)

// fp16 chunk sizes (u32 words per 128x32 chunk)
#define ACH 2048
#define BCH 2048

static const size_t POINTS_ELEMS = (size_t)MM * VV;

// ---------------- scratch ----------------
__device__ __align__(128) float g_dec_in[LL*NN*HH];
__device__ __align__(128) float g_gi[LL*NN*H3];
__device__ __align__(128) float g_h[LL*NN*HH];
__device__ __align__(128) float g_hprev[NN*HH];
__device__ __align__(128) float g_gh[NN*H3];
__device__ __align__(128) float g_prob[LL*NN*TT];
__device__ __align__(128) float g_ctx[LL*NN*HH];
__device__ __align__(128) float g_switch[LL*NN];

// fragment-permuted fp16 operand buffers
__device__ __align__(128) uint32_t cA_dec[NBM_BIG*NCH*ACH];
__device__ __align__(128) uint32_t cA_big[NBM_BIG*NCH*ACH];
__device__ __align__(128) uint32_t cA_h  [NBM_H  *NCH*ACH];
__device__ __align__(128) uint32_t cB_emb[NBN_EMB*NCH*BCH];
__device__ __align__(128) uint32_t cB_wih[NBN_W  *NCH*BCH];
__device__ __align__(128) uint32_t cB_whh[NBN_W  *NCH*BCH];

// ---------------- helpers ----------------
__device__ __forceinline__ float warpMax(float v){
    #pragma unroll
    for (int o = 16; o; o >>= 1) v = fmaxf(v, __shfl_xor_sync(0xffffffffu, v, o));
    return v;
}
__device__ __forceinline__ float warpSum(float v){
    #pragma unroll
    for (int o = 16; o; o >>= 1) v += __shfl_xor_sync(0xffffffffu, v, o);
    return v;
}
__device__ __forceinline__ float sigmoidf(float x){ return 1.f / (1.f + expf(-x)); }
__device__ __forceinline__ uint32_t packh2(float a, float b){
    __half2 h = __floats2half2_rn(a, b);
    return *reinterpret_cast<uint32_t*>(&h);
}
__device__ __forceinline__ void mma_f16(float* d, const uint32_t* a, const uint32_t* b){
    asm volatile(
        "mma.sync.aligned.m16n8k16.row.col.f32.f16.f16.f32 "
        "{%0,%1,%2,%3}, {%4,%5,%6,%7}, {%8,%9}, {%0,%1,%2,%3};\n"
        : "+f"(d[0]), "+f"(d[1]), "+f"(d[2]), "+f"(d[3])
        : "r"(a[0]), "r"(a[1]), "r"(a[2]), "r"(a[3]), "r"(b[0]), "r"(b[1]));
}
__device__ __forceinline__ uint32_t smem_u32(const void* p){
    uint32_t a;
    asm("{ .reg .u64 t; cvta.to.shared.u64 t, %1; cvt.u32.u64 %0, t; }" : "=r"(a) : "l"(p));
    return a;
}
__device__ __forceinline__ void cp16(uint32_t saddr, const void* g){
    asm volatile("cp.async.ca.shared.global [%0], [%1], 16;" :: "r"(saddr), "l"(g) : "memory");
}
__device__ __forceinline__ void cp_commit(){ asm volatile("cp.async.commit_group;" ::: "memory"); }
template<int W> __device__ __forceinline__ void cp_wait(){
    asm volatile("cp.async.wait_group %0;" :: "n"(W) : "memory");
}

// fp16 A-fragment store: element pair (r, k0), (r, k0+1), k0 even.
// Layout per 128x32 chunk: [m_tile(8)][kt(2)][lane(32)][reg(4)] u32
__device__ __forceinline__ void storeA2(uint32_t* dst, int r, int k0, float v0, float v1){
    int blk = r >> 7, rl = r & 127;
    int m_tile = rl >> 4, rr = rl & 15;
    int c = k0 >> 5, kk = k0 & 31;
    int kt = kk >> 4, kin2 = kk & 15;
    int khalf = kin2 >> 3, kin = kin2 & 7;
    int reg = khalf*2 + (rr >= 8 ? 1 : 0);
    int lane = ((rr & 7) << 2) + (kin >> 1);
    dst[(size_t)(blk*NCH + c)*ACH + ((m_tile*2 + kt)*32 + lane)*4 + reg] = packh2(v0, v1);
}

// ---------------- conv_B: weights -> permuted fp16 ----------------
// Layout per 128x32 chunk: [n_tile(16)][kt(2)][lane(32)][reg(2)] u32
__global__ void conv_B(const float* __restrict__ src, uint32_t* __restrict__ dst,
                       int R, int RP){
    int idx = blockIdx.x * blockDim.x + threadIdx.x;
    const int nq = NCH*8;
    if (idx >= RP*nq) return;
    int r = idx / nq, q = idx % nq;
    int k = q << 2;
    float4 v = make_float4(0.f,0.f,0.f,0.f);
    if (r < R && k < HH) v = *(const float4*)(src + (size_t)r*HH + k);
    int blk = r >> 7, rl = r & 127;
    int n_tile = rl >> 3, nn = rl & 7;
    int c = k >> 5, kk = k & 31;
    int kt = kk >> 4, kin2 = kk & 15;
    int khalf = kin2 >> 3, kin = kin2 & 7;   // kin in {0, 4}
    int reg = khalf;
    int t0 = kin >> 1;                        // {0, 2}
    size_t base = (size_t)(blk*NCH + c)*BCH + ((n_tile*2 + kt)*32 + (nn << 2) + t0)*2 + reg;
    dst[base    ] = packh2(v.x, v.y);
    dst[base + 2] = packh2(v.z, v.w);
}

// =====================================================================
// fp16 MMA GEMM: pre-permuted operands, 2-stage cp.async. Block 128xTNB.
// =====================================================================
template<int TNB, bool BIAS>
__global__ __launch_bounds__(256) void mma_gemm2(
    const uint32_t* __restrict__ Af, const uint32_t* __restrict__ Bf,
    const float* __restrict__ bias, float* __restrict__ C,
    int M, int Nn, int ldc)
{
    constexpr int BS = TNB*16;        // B stage size in u32 (128->2048, 64->1024)
    constexpr int NI = TNB/16;        // B frags per warp
    extern __shared__ uint32_t sm2[];
    uint32_t sbase = smem_u32(sm2);
    int tid = threadIdx.x, lane = tid & 31, wid = tid >> 5;
    int wm = wid & 3, wn = wid >> 2;

    const uint32_t* gA = Af + (size_t)blockIdx.y * NCH * ACH;
    const uint32_t* gB;
    if (TNB == 128) gB = Bf + (size_t)blockIdx.x * NCH * BCH;
    else            gB = Bf + (size_t)(blockIdx.x >> 1) * NCH * BCH + (blockIdx.x & 1) * 1024;

    float d[2][NI][4];
    #pragma unroll
    for (int mi = 0; mi < 2; mi++)
        #pragma unroll
        for (int ni = 0; ni < NI; ni++)
            #pragma unroll
            for (int q = 0; q < 4; q++) d[mi][ni][q] = 0.f;

    auto pre = [&](int c){
        int s = c & 1;
        uint32_t sA = sbase + (uint32_t)s*(ACH*4);
        uint32_t sB = sbase + 2u*ACH*4 + (uint32_t)s*(BS*4);
        const uint32_t* a = gA + c*ACH;
        const uint32_t* b = gB + c*BCH;
        #pragma unroll
        for (int u = 0; u < 2; u++){
            int off = (tid + (u << 8)) << 2;
            cp16(sA + (off << 2), a + off);
        }
        #pragma unroll
        for (int u = 0; u < TNB/64; u++){
            int off = (tid + (u << 8)) << 2;
            cp16(sB + (off << 2), b + off);
        }
        cp_commit();
    };

    pre(0);
    for (int c = 0; c < NCH; c++){
        if (c + 1 < NCH){ pre(c + 1); cp_wait<1>(); }
        else cp_wait<0>();
        __syncthreads();
        const uint32_t* bA = sm2 + (c & 1)*ACH;
        const uint32_t* bB = sm2 + 2*ACH + (c & 1)*BS;
        #pragma unroll
        for (int kt = 0; kt < 2; kt++){
            uint32_t a[2][4], b[NI][2];
            #pragma unroll
            for (int mi = 0; mi < 2; mi++)
                *(uint4*)a[mi] = *(const uint4*)&bA[(((wm*2+mi)*2 + kt)*32 + lane)*4];
            #pragma unroll
            for (int ni = 0; ni < NI; ni++)
                *(uint2*)b[ni] = *(const uint2*)&bB[(((wn*NI+ni)*2 + kt)*32 + lane)*2];
            #pragma unroll
            for (int mi = 0; mi < 2; mi++)
                #pragma unroll
                for (int ni = 0; ni < NI; ni++)
                    mma_f16(d[mi][ni], a[mi], b[ni]);
        }
        __syncthreads();
    }

    int grp = lane >> 2, qid = lane & 3;
    int tile_m = blockIdx.y * 128, tile_n = blockIdx.x * TNB;
    #pragma unroll
    for (int mi = 0; mi < 2; mi++){
        int row0 = tile_m + wm*32 + mi*16 + grp;
        #pragma unroll
        for (int ni = 0; ni < NI; ni++){
            int col = tile_n + wn*(TNB/2) + ni*8 + qid*2;
            if (col < Nn){
                float b0 = 0.f, b1 = 0.f;
                if (BIAS){ b0 = bias[col]; b1 = bias[col+1]; }
                if (row0 < M){
                    float2 v = make_float2(d[mi][ni][0] + b0, d[mi][ni][1] + b1);
                    *(float2*)(C + (size_t)row0*ldc + col) = v;
                }
                if (row0 + 8 < M){
                    float2 v = make_float2(d[mi][ni][2] + b0, d[mi][ni][3] + b1);
                    *(float2*)(C + (size_t)(row0+8)*ldc + col) = v;
                }
            }
        }
    }
}

#define MG2_SMEM_128 (2*(ACH+2048)*4)   // 32768
#define MG2_SMEM_64  (2*(ACH+1024)*4)   // 24576

// ---------------- K1: decoder inputs (pairwise, + fused fp16 A) ----------------
__global__ void k_decin(const float* __restrict__ emb, const float* __restrict__ slot_emb,
                        const int* __restrict__ dom, const int* __restrict__ slo,
                        const int* __restrict__ tgt){
    int idx = blockIdx.x * blockDim.x + threadIdx.x;
    const int HP = HH2/2;
    if (idx >= LL*NN*HP) return;
    int j = idx % HP; int r = idx / HP; int n = r % NN; int l = r / NN;
    int k0 = j << 1;
    float v0 = 0.f, v1 = 0.f;
    if (k0 < HH){
        int s = n / BB, b = n % BB;
        if (l == 0){
            float2 d0 = *(const float2*)(slot_emb + (size_t)dom[s]*HH + k0);
            float2 d1 = *(const float2*)(slot_emb + (size_t)slo[s]*HH + k0);
            v0 = d0.x + d1.x; v1 = d0.y + d1.y;
        } else {
            int tok = tgt[(b*NSLOT + s)*LL + (l-1)];
            float2 e = *(const float2*)(emb + (size_t)tok*HH + k0);
            v0 = e.x; v1 = e.y;
        }
        *(float2*)(g_dec_in + (size_t)r*HH + k0) = make_float2(v0, v1);
    }
    storeA2(cA_dec, r, k0, v0, v1);
}

// ---------------- K2: init hidden (pairwise) ----------------
__global__ void k_hinit(const float* __restrict__ enc_hidden){
    int idx = blockIdx.x * blockDim.x + threadIdx.x;
    const int HP = HH2/2;
    if (idx >= NN*HP) return;
    int n = idx / HP, j = idx % HP;
    int k0 = j << 1;
    float v0 = 0.f, v1 = 0.f;
    if (k0 < HH){
        float2 e = *(const float2*)(enc_hidden + (size_t)(n % BB)*HH + k0);
        v0 = e.x; v1 = e.y;
        *(float2*)(g_hprev + (size_t)n*HH + k0) = e;
    }
    storeA2(cA_h, n, k0, v0, v1);
}

// ---------------- K3: GRU gate fuse (pairwise, + fused fp16 A) ----------------
__global__ void k_gate(int l){
    int idx = blockIdx.x * blockDim.x + threadIdx.x;
    const int HP = HH2/2;
    if (idx >= NN*HP) return;
    int n = idx / HP, j = idx % HP;
    int k0 = j << 1;
    if (k0 >= HH){
        storeA2(cA_h,   n,        k0, 0.f, 0.f);
        storeA2(cA_big, n*LL + l, k0, 0.f, 0.f);
        return;
    }
    const float* gi = g_gi + (size_t)(l*NN + n)*H3;
    const float* gh = g_gh + (size_t)n*H3;
    float2 gir = *(const float2*)(gi + k0);
    float2 giz = *(const float2*)(gi + HH + k0);
    float2 gin = *(const float2*)(gi + 2*HH + k0);
    float2 ghr = *(const float2*)(gh + k0);
    float2 ghz = *(const float2*)(gh + HH + k0);
    float2 ghn = *(const float2*)(gh + 2*HH + k0);
    float2 hp  = *(const float2*)(g_hprev + (size_t)n*HH + k0);
    float r0 = sigmoidf(gir.x + ghr.x), r1 = sigmoidf(gir.y + ghr.y);
    float z0 = sigmoidf(giz.x + ghz.x), z1 = sigmoidf(giz.y + ghz.y);
    float n0 = tanhf(gin.x + r0*ghn.x), n1 = tanhf(gin.y + r1*ghn.y);
    float h0 = (1.f - z0)*n0 + z0*hp.x;
    float h1 = (1.f - z1)*n1 + z1*hp.y;
    *(float2*)(g_h + (size_t)(l*NN + n)*HH + k0) = make_float2(h0, h1);
    *(float2*)(g_hprev + (size_t)n*HH + k0) = make_float2(h0, h1);
    storeA2(cA_h,   n,        k0, h0, h1);
    storeA2(cA_big, n*LL + l, k0, h0, h1);
}

// ---------------- K4: attention ----------------
#define ENC_PAD 68
__global__ __launch_bounds__(256) void k_attn(const float* __restrict__ enc_out,
                                              const int* __restrict__ lens){
    extern __shared__ float sm[];
    float* sh_h   = sm;
    float* sh_enc = sm + NSLOT*HH;
    float* sh_sc  = sh_enc + TT*ENC_PAD;
    __shared__ float red[8];
    __shared__ float s_mx, s_sum;

    int l  = blockIdx.x / BB;
    int bb = blockIdx.x % BB;
    int tid = threadIdx.x;
    int lane = tid & 31, wrp = tid >> 5;
    int t = tid;

    for (int i = tid; i < NSLOT*HH; i += 256){
        int s = i / HH, h = i % HH;
        sh_h[i] = g_h[(size_t)(l*NN + s*BB + bb)*HH + h];
    }
    for (int i = tid; i < NSLOT*TT; i += 256) sh_sc[i] = 0.f;
    __syncthreads();

    for (int kc = 0; kc < HH; kc += 64){
        int kw = min(64, HH - kc);
        for (int i = tid; i < TT*kw; i += 256){
            int tt2 = i / kw, kk = i % kw;
            sh_enc[tt2*ENC_PAD + kk] = enc_out[((size_t)bb*TT + tt2)*HH + kc + kk];
        }
        __syncthreads();
        for (int sg = 0; sg < NSLOT; sg += 10){
            float acc[10];
            #pragma unroll
            for (int u = 0; u < 10; u++) acc[u] = 0.f;
            for (int kk = 0; kk < kw; kk += 4){
                float4 e = *(const float4*)&sh_enc[t*ENC_PAD + kk];
                #pragma unroll
                for (int u = 0; u < 10; u++){
                    float4 hv = *(const float4*)&sh_h[(sg+u)*HH + kc + kk];
                    acc[u] += hv.x*e.x + hv.y*e.y + hv.z*e.z + hv.w*e.w;
                }
            }
            #pragma unroll
            for (int u = 0; u < 10; u++) sh_sc[(sg+u)*TT + t] += acc[u];
        }
        __syncthreads();
    }

    int len = lens[bb];
    for (int s = 0; s < NSLOT; s++){
        float v = (t < len) ? sh_sc[s*TT + t] : -1e9f;
        float m = warpMax(v);
        if (lane == 0) red[wrp] = m;
        __syncthreads();
        if (tid == 0){
            float mm = red[0];
            #pragma unroll
            for (int i = 1; i < 8; i++) mm = fmaxf(mm, red[i]);
            s_mx = mm;
        }
        __syncthreads();
        float p = expf(v - s_mx);
        float su = warpSum(p);
        if (lane == 0) red[wrp] = su;
        __syncthreads();
        if (tid == 0){
            float ss = 0.f;
            #pragma unroll
            for (int i = 0; i < 8; i++) ss += red[i];
            s_sum = ss;
        }
        __syncthreads();
        p /= s_sum;
        sh_sc[s*TT + t] = p;
        g_prob[(size_t)(l*NN + s*BB + bb)*TT + t] = p;
        __syncthreads();
    }

    for (int hc = 0; hc < HH; hc += 64){
        int hw = min(64, HH - hc);
        __syncthreads();
        for (int i = tid; i < TT*hw; i += 256){
            int tt2 = i / hw, hh = i % hw;
            sh_enc[tt2*ENC_PAD + hh] = enc_out[((size_t)bb*TT + tt2)*HH + hc + hh];
        }
        __syncthreads();
        int nq = NSLOT * (hw >> 2);
        for (int oi = tid; oi < nq; oi += 256){
            int s  = oi / (hw >> 2);
            int h4 = (oi % (hw >> 2)) * 4;
            float4 a = make_float4(0,0,0,0);
            for (int tt2 = 0; tt2 < TT; tt2++){
                float p = sh_sc[s*TT + tt2];
                float4 e = *(const float4*)&sh_enc[tt2*ENC_PAD + h4];
                a.x += p*e.x; a.y += p*e.y; a.z += p*e.z; a.w += p*e.w;
            }
            *(float4*)&g_ctx[(size_t)(l*NN + s*BB + bb)*HH + hc + h4] = a;
        }
    }
}

// ---------------- K5: switch ----------------
__global__ void k_switch(const float* __restrict__ w_ratio, const float* __restrict__ b_ratio){
    int row = blockIdx.x;
    int tid = threadIdx.x;
    const float* h = g_h      + (size_t)row*HH;
    const float* c = g_ctx    + (size_t)row*HH;
    const float* x = g_dec_in + (size_t)row*HH;
    float a = 0.f;
    for (int i = tid; i < HH; i += 128)
        a += h[i]*w_ratio[i] + c[i]*w_ratio[HH + i] + x[i]*w_ratio[2*HH + i];
    __shared__ float red[4];
    a = warpSum(a);
    if ((tid & 31) == 0) red[tid >> 5] = a;
    __syncthreads();
    if (tid == 0){
        float tot = red[0] + red[1] + red[2] + red[3] + b_ratio[0];
        g_switch[row] = sigmoidf(tot);
    }
}

// ---------------- K6: gates head ----------------
__global__ void k_gates(const float* __restrict__ w_gate, const float* __restrict__ b_gate,
                        float* __restrict__ out_gates){
    int n = blockIdx.x;
    int tid = threadIdx.x;
    const float* c = g_ctx + (size_t)n*HH;
    float a0 = 0.f, a1 = 0.f, a2 = 0.f;
    for (int i = tid; i < HH; i += 128){
        float cv = c[i];
        a0 += cv * w_gate[i];
        a1 += cv * w_gate[HH + i];
        a2 += cv * w_gate[2*HH + i];
    }
    __shared__ float red[3][4];
    a0 = warpSum(a0); a1 = warpSum(a1); a2 = warpSum(a2);
    if ((tid & 31) == 0){
        int w = tid >> 5;
        red[0][w] = a0; red[1][w] = a1; red[2][w] = a2;
    }
    __syncthreads();
    if (tid < GG){
        float tot = red[tid][0] + red[tid][1] + red[tid][2] + red[tid][3] + b_gate[tid];
        out_gates[(size_t)n*GG + tid] = tot;
    }
}

// ---------------- K8: softmax + pointer scatter + mix ----------------
__global__ __launch_bounds__(256) void k_softmix(float* __restrict__ out,
                                                 const int* __restrict__ story){
    extern __shared__ float smx[];
    float* pctx = smx;
    float* vals = smx + VV;
    __shared__ float red[8];
    __shared__ float s_mx, s_sum;
    int m = blockIdx.x, tid = threadIdx.x;
    int lane = tid & 31, wrp = tid >> 5;
    int n = m / LL, l = m % LL, bb = n % BB;
    int rowa = l*NN + n;
    float sw = g_switch[rowa];

    for (int i = tid; i < VV; i += 256) pctx[i] = 0.f;
    float* base = out + (size_t)m*VV;
    float lm = -INFINITY;
    for (int v = tid; v < VV; v += 256){
        float x = base[v];
        vals[v] = x;
        lm = fmaxf(lm, x);
    }
    __syncthreads();
    {
        float p = g_prob[(size_t)rowa*TT + tid];
        int c = story[bb*TT + tid];
        atomicAdd(&pctx[c], p);
    }
    lm = warpMax(lm);
    if (lane == 0) red[wrp] = lm;
    __syncthreads();
    if (tid == 0){
        float mm = red[0];
        #pragma unroll
        for (int i = 1; i < 8; i++) mm = fmaxf(mm, red[i]);
        s_mx = mm;
    }
    __syncthreads();
    float mx = s_mx;
    float ls = 0.f;
    for (int v = tid; v < VV; v += 256){
        float e = __expf(vals[v] - mx);
        vals[v] = e;
        ls += e;
    }
    ls = warpSum(ls);
    if (lane == 0) red[wrp] = ls;
    __syncthreads();
    if (tid == 0){
        float ss = 0.f;
        #pragma unroll
        for (int i = 0; i < 8; i++) ss += red[i];
        s_sum = ss;
    }
    __syncthreads();
    float scale = sw / s_sum;
    float osw = 1.f - sw;
    for (int v = tid; v < VV; v += 256)
        base[v] = vals[v] * scale + osw * pctx[v];
}

// ---------------- launch ----------------
extern "C" void kernel_launch(void* const* d_in, const int* in_sizes, int n_in,
                              void* d_out, int out_size){
    const float* enc_hidden = (const float*)d_in[0];
    const float* enc_out    = (const float*)d_in[1];
    const float* emb        = (const float*)d_in[2];
    const float* w_ih       = (const float*)d_in[3];
    const float* w_hh       = (const float*)d_in[4];
    const float* b_ih       = (const float*)d_in[5];
    const float* b_hh       = (const float*)d_in[6];
    const float* w_ratio    = (const float*)d_in[7];
    const float* b_ratio    = (const float*)d_in[8];
    const float* w_gate     = (const float*)d_in[9];
    const float* b_gate     = (const float*)d_in[10];
    const float* slot_emb   = (const float*)d_in[11];
    const int*   lens       = (const int*)d_in[12];
    const int*   story      = (const int*)d_in[13];
    const int*   tgt        = (const int*)d_in[14];
    const int*   dom        = (const int*)d_in[15];
    const int*   slo        = (const int*)d_in[16];
    float* out = (float*)d_out;

    float *p_gi, *p_gh;
    uint32_t *pA_dec, *pA_big, *pA_h, *pB_emb, *pB_wih, *pB_whh;
    cudaGetSymbolAddress((void**)&p_gi,    g_gi);
    cudaGetSymbolAddress((void**)&p_gh,    g_gh);
    cudaGetSymbolAddress((void**)&pA_dec,  cA_dec);
    cudaGetSymbolAddress((void**)&pA_big,  cA_big);
    cudaGetSymbolAddress((void**)&pA_h,    cA_h);
    cudaGetSymbolAddress((void**)&pB_emb,  cB_emb);
    cudaGetSymbolAddress((void**)&pB_wih,  cB_wih);
    cudaGetSymbolAddress((void**)&pB_whh,  cB_whh);

    const int ATTN_SMEM = (NSLOT*HH + TT*ENC_PAD + NSLOT*TT) * 4;
    const int SMX_SMEM  = 2*VV*4;
    cudaFuncSetAttribute(k_attn, cudaFuncAttributeMaxDynamicSharedMemorySize, ATTN_SMEM);
    cudaFuncSetAttribute(k_softmix, cudaFuncAttributeMaxDynamicSharedMemorySize, SMX_SMEM);
    cudaFuncSetAttribute((const void*)mma_gemm2<128,true>,  cudaFuncAttributeMaxDynamicSharedMemorySize, MG2_SMEM_128);
    cudaFuncSetAttribute((const void*)mma_gemm2<128,false>, cudaFuncAttributeMaxDynamicSharedMemorySize, MG2_SMEM_128);
    cudaFuncSetAttribute((const void*)mma_gemm2<64,true>,   cudaFuncAttributeMaxDynamicSharedMemorySize, MG2_SMEM_64);

    const int nq = NCH*8;
    const int HP = HH2/2;

    // 0) weight conversions
    conv_B<<<(NBN_EMB*128*nq + 255)/256, 256>>>(emb,  pB_emb, VV,  NBN_EMB*128);
    conv_B<<<(NBN_W  *128*nq + 255)/256, 256>>>(w_ih, pB_wih, H3,  NBN_W*128);
    conv_B<<<(NBN_W  *128*nq + 255)/256, 256>>>(w_hh, pB_whh, H3,  NBN_W*128);

    // 1) decoder inputs + h0 (fused permuted-A writes)
    k_decin<<<(LL*NN*HP + 255)/256, 256>>>(emb, slot_emb, dom, slo, tgt);
    k_hinit<<<(NN*HP + 255)/256, 256>>>(enc_hidden);

    // 2) input-side gates, all steps
    {
        dim3 grid(NBN_W, NBM_BIG);
        mma_gemm2<128,true><<<grid, 256, MG2_SMEM_128>>>(pA_dec, pB_wih, b_ih, p_gi, MM, H3, H3);
    }

    // 3) GRU recurrence (TN=64 -> 76 blocks)
    for (int l = 0; l < LL; l++){
        dim3 grid((H3 + 63)/64, NBM_H);
        mma_gemm2<64,true><<<grid, 256, MG2_SMEM_64>>>(pA_h, pB_whh, b_hh, p_gh, NN, H3, H3);
        k_gate<<<(NN*HP + 255)/256, 256>>>(l);
    }

    // 4) attention
    k_attn<<<LL*BB, 256, ATTN_SMEM>>>(enc_out, lens);

    // 5) switch; 6) gates head
    k_switch<<<LL*NN, 128>>>(w_ratio, b_ratio);
    k_gates<<<NN, 128>>>(w_gate, b_gate, out + POINTS_ELEMS);

    // 7) big vocab GEMM (fp16), logits into d_out
    {
        dim3 grid(NBN_EMB, NBM_BIG);
        mma_gemm2<128,false><<<grid, 256, MG2_SMEM_128>>>(pA_big, pB_emb, nullptr, out, MM, VV, VV);
    }

    // 8) softmax + pointer scatter + mix, in place
    k_softmix<<<MM, 256, SMX_SMEM>>>(out, story);
}

// round 8
// speedup vs baseline: 2.0540x; 1.2273x over previous
#include <cuda_runtime.h>
#include <cuda_fp16.h>
#include <cstdint>
#include <math.h>

// ---------------- problem constants ----------------
#define BB 16
#define TT 256
#define VV 18000
#define NSLOT 30
#define LL 10
#define GG 3
#define HH 400
#define HH2 416           // K padded to NCH*32
#define NN (NSLOT*BB)     // 480
#define MM (LL*NN)        // 4800
#define H3 (3*HH)         // 1200
#define NCH 13

#define NBM_BIG 38        // ceil(4800/128)
#define NBM_H   4
#define NBN_EMB 141       // ceil(18000/128)
#define NBN_W   10        // ceil(1200/128)

// fp16 chunk sizes (u32 words per 128x32 chunk)
#define ACH 2048
#define BCH 2048

static const size_t POINTS_ELEMS = (size_t)MM * VV;

// ---------------- scratch ----------------
__device__ __align__(128) float g_dec_in[LL*NN*HH];
__device__ __align__(128) float g_gi[LL*NN*H3];
__device__ __align__(128) float g_h[LL*NN*HH];
__device__ __align__(128) float g_hprev[NN*HH];
__device__ __align__(128) float g_gh[NN*H3];
__device__ __align__(128) float g_prob[LL*NN*TT];
__device__ __align__(128) float g_ctx[LL*NN*HH];
__device__ __align__(128) float g_switch[LL*NN];

// fragment-permuted fp16 operand buffers
__device__ __align__(128) uint32_t cA_dec[NBM_BIG*NCH*ACH];
__device__ __align__(128) uint32_t cA_big[NBM_BIG*NCH*ACH];
__device__ __align__(128) uint32_t cA_h  [NBM_H  *NCH*ACH];
__device__ __align__(128) uint32_t cB_emb[NBN_EMB*NCH*BCH];
__device__ __align__(128) uint32_t cB_wih[NBN_W  *NCH*BCH];
__device__ __align__(128) uint32_t cB_whh[NBN_W  *NCH*BCH];

// ---------------- helpers ----------------
__device__ __forceinline__ float warpMax(float v){
    #pragma unroll
    for (int o = 16; o; o >>= 1) v = fmaxf(v, __shfl_xor_sync(0xffffffffu, v, o));
    return v;
}
__device__ __forceinline__ float warpSum(float v){
    #pragma unroll
    for (int o = 16; o; o >>= 1) v += __shfl_xor_sync(0xffffffffu, v, o);
    return v;
}
__device__ __forceinline__ float sigmoidf(float x){ return 1.f / (1.f + expf(-x)); }
__device__ __forceinline__ uint32_t packh2(float a, float b){
    __half2 h = __floats2half2_rn(a, b);
    return *reinterpret_cast<uint32_t*>(&h);
}
__device__ __forceinline__ void mma_f16(float* d, const uint32_t* a, const uint32_t* b){
    asm volatile(
        "mma.sync.aligned.m16n8k16.row.col.f32.f16.f16.f32 "
        "{%0,%1,%2,%3}, {%4,%5,%6,%7}, {%8,%9}, {%0,%1,%2,%3};\n"
        : "+f"(d[0]), "+f"(d[1]), "+f"(d[2]), "+f"(d[3])
        : "r"(a[0]), "r"(a[1]), "r"(a[2]), "r"(a[3]), "r"(b[0]), "r"(b[1]));
}
__device__ __forceinline__ uint32_t smem_u32(const void* p){
    uint32_t a;
    asm("{ .reg .u64 t; cvta.to.shared.u64 t, %1; cvt.u32.u64 %0, t; }" : "=r"(a) : "l"(p));
    return a;
}
__device__ __forceinline__ void cp16(uint32_t saddr, const void* g){
    asm volatile("cp.async.ca.shared.global [%0], [%1], 16;" :: "r"(saddr), "l"(g) : "memory");
}
__device__ __forceinline__ void cp_commit(){ asm volatile("cp.async.commit_group;" ::: "memory"); }
template<int W> __device__ __forceinline__ void cp_wait(){
    asm volatile("cp.async.wait_group %0;" :: "n"(W) : "memory");
}

// fp16 A-fragment store
__device__ __forceinline__ void storeA2(uint32_t* dst, int r, int k0, float v0, float v1){
    int blk = r >> 7, rl = r & 127;
    int m_tile = rl >> 4, rr = rl & 15;
    int c = k0 >> 5, kk = k0 & 31;
    int kt = kk >> 4, kin2 = kk & 15;
    int khalf = kin2 >> 3, kin = kin2 & 7;
    int reg = khalf*2 + (rr >= 8 ? 1 : 0);
    int lane = ((rr & 7) << 2) + (kin >> 1);
    dst[(size_t)(blk*NCH + c)*ACH + ((m_tile*2 + kt)*32 + lane)*4 + reg] = packh2(v0, v1);
}

// ---------------- conv_B ----------------
__global__ void conv_B(const float* __restrict__ src, uint32_t* __restrict__ dst,
                       int R, int RP){
    int idx = blockIdx.x * blockDim.x + threadIdx.x;
    const int nq = NCH*8;
    if (idx >= RP*nq) return;
    int r = idx / nq, q = idx % nq;
    int k = q << 2;
    float4 v = make_float4(0.f,0.f,0.f,0.f);
    if (r < R && k < HH) v = *(const float4*)(src + (size_t)r*HH + k);
    int blk = r >> 7, rl = r & 127;
    int n_tile = rl >> 3, nn = rl & 7;
    int c = k >> 5, kk = k & 31;
    int kt = kk >> 4, kin2 = kk & 15;
    int khalf = kin2 >> 3, kin = kin2 & 7;
    int reg = khalf;
    int t0 = kin >> 1;
    size_t base = (size_t)(blk*NCH + c)*BCH + ((n_tile*2 + kt)*32 + (nn << 2) + t0)*2 + reg;
    dst[base    ] = packh2(v.x, v.y);
    dst[base + 2] = packh2(v.z, v.w);
}

// =====================================================================
// fp16 MMA GEMM (proven R7 config — unchanged)
// =====================================================================
template<int TNB, bool BIAS>
__global__ __launch_bounds__(256) void mma_gemm2(
    const uint32_t* __restrict__ Af, const uint32_t* __restrict__ Bf,
    const float* __restrict__ bias, float* __restrict__ C,
    int M, int Nn, int ldc)
{
    constexpr int BS = TNB*16;
    constexpr int NI = TNB/16;
    extern __shared__ uint32_t sm2[];
    uint32_t sbase = smem_u32(sm2);
    int tid = threadIdx.x, lane = tid & 31, wid = tid >> 5;
    int wm = wid & 3, wn = wid >> 2;

    const uint32_t* gA = Af + (size_t)blockIdx.y * NCH * ACH;
    const uint32_t* gB;
    if (TNB == 128) gB = Bf + (size_t)blockIdx.x * NCH * BCH;
    else            gB = Bf + (size_t)(blockIdx.x >> 1) * NCH * BCH + (blockIdx.x & 1) * 1024;

    float d[2][NI][4];
    #pragma unroll
    for (int mi = 0; mi < 2; mi++)
        #pragma unroll
        for (int ni = 0; ni < NI; ni++)
            #pragma unroll
            for (int q = 0; q < 4; q++) d[mi][ni][q] = 0.f;

    auto pre = [&](int c){
        int s = c & 1;
        uint32_t sA = sbase + (uint32_t)s*(ACH*4);
        uint32_t sB = sbase + 2u*ACH*4 + (uint32_t)s*(BS*4);
        const uint32_t* a = gA + c*ACH;
        const uint32_t* b = gB + c*BCH;
        #pragma unroll
        for (int u = 0; u < 2; u++){
            int off = (tid + (u << 8)) << 2;
            cp16(sA + (off << 2), a + off);
        }
        #pragma unroll
        for (int u = 0; u < TNB/64; u++){
            int off = (tid + (u << 8)) << 2;
            cp16(sB + (off << 2), b + off);
        }
        cp_commit();
    };

    pre(0);
    for (int c = 0; c < NCH; c++){
        if (c + 1 < NCH){ pre(c + 1); cp_wait<1>(); }
        else cp_wait<0>();
        __syncthreads();
        const uint32_t* bA = sm2 + (c & 1)*ACH;
        const uint32_t* bB = sm2 + 2*ACH + (c & 1)*BS;
        #pragma unroll
        for (int kt = 0; kt < 2; kt++){
            uint32_t a[2][4], b[NI][2];
            #pragma unroll
            for (int mi = 0; mi < 2; mi++)
                *(uint4*)a[mi] = *(const uint4*)&bA[(((wm*2+mi)*2 + kt)*32 + lane)*4];
            #pragma unroll
            for (int ni = 0; ni < NI; ni++)
                *(uint2*)b[ni] = *(const uint2*)&bB[(((wn*NI+ni)*2 + kt)*32 + lane)*2];
            #pragma unroll
            for (int mi = 0; mi < 2; mi++)
                #pragma unroll
                for (int ni = 0; ni < NI; ni++)
                    mma_f16(d[mi][ni], a[mi], b[ni]);
        }
        __syncthreads();
    }

    int grp = lane >> 2, qid = lane & 3;
    int tile_m = blockIdx.y * 128, tile_n = blockIdx.x * TNB;
    #pragma unroll
    for (int mi = 0; mi < 2; mi++){
        int row0 = tile_m + wm*32 + mi*16 + grp;
        #pragma unroll
        for (int ni = 0; ni < NI; ni++){
            int col = tile_n + wn*(TNB/2) + ni*8 + qid*2;
            if (col < Nn){
                float b0 = 0.f, b1 = 0.f;
                if (BIAS){ b0 = bias[col]; b1 = bias[col+1]; }
                if (row0 < M){
                    float2 v = make_float2(d[mi][ni][0] + b0, d[mi][ni][1] + b1);
                    *(float2*)(C + (size_t)row0*ldc + col) = v;
                }
                if (row0 + 8 < M){
                    float2 v = make_float2(d[mi][ni][2] + b0, d[mi][ni][3] + b1);
                    *(float2*)(C + (size_t)(row0+8)*ldc + col) = v;
                }
            }
        }
    }
}

#define MG2_SMEM_128 (2*(ACH+2048)*4)   // 32768
#define MG2_SMEM_64  (2*(ACH+1024)*4)   // 24576

// ---------------- K1: decoder inputs ----------------
__global__ void k_decin(const float* __restrict__ emb, const float* __restrict__ slot_emb,
                        const int* __restrict__ dom, const int* __restrict__ slo,
                        const int* __restrict__ tgt){
    int idx = blockIdx.x * blockDim.x + threadIdx.x;
    const int HP = HH2/2;
    if (idx >= LL*NN*HP) return;
    int j = idx % HP; int r = idx / HP; int n = r % NN; int l = r / NN;
    int k0 = j << 1;
    float v0 = 0.f, v1 = 0.f;
    if (k0 < HH){
        int s = n / BB, b = n % BB;
        if (l == 0){
            float2 d0 = *(const float2*)(slot_emb + (size_t)dom[s]*HH + k0);
            float2 d1 = *(const float2*)(slot_emb + (size_t)slo[s]*HH + k0);
            v0 = d0.x + d1.x; v1 = d0.y + d1.y;
        } else {
            int tok = tgt[(b*NSLOT + s)*LL + (l-1)];
            float2 e = *(const float2*)(emb + (size_t)tok*HH + k0);
            v0 = e.x; v1 = e.y;
        }
        *(float2*)(g_dec_in + (size_t)r*HH + k0) = make_float2(v0, v1);
    }
    storeA2(cA_dec, r, k0, v0, v1);
}

// ---------------- K2: init hidden ----------------
__global__ void k_hinit(const float* __restrict__ enc_hidden){
    int idx = blockIdx.x * blockDim.x + threadIdx.x;
    const int HP = HH2/2;
    if (idx >= NN*HP) return;
    int n = idx / HP, j = idx % HP;
    int k0 = j << 1;
    float v0 = 0.f, v1 = 0.f;
    if (k0 < HH){
        float2 e = *(const float2*)(enc_hidden + (size_t)(n % BB)*HH + k0);
        v0 = e.x; v1 = e.y;
        *(float2*)(g_hprev + (size_t)n*HH + k0) = e;
    }
    storeA2(cA_h, n, k0, v0, v1);
}

// ---------------- K3: GRU gate fuse ----------------
__global__ void k_gate(int l){
    int idx = blockIdx.x * blockDim.x + threadIdx.x;
    const int HP = HH2/2;
    if (idx >= NN*HP) return;
    int n = idx / HP, j = idx % HP;
    int k0 = j << 1;
    if (k0 >= HH){
        storeA2(cA_h,   n,        k0, 0.f, 0.f);
        storeA2(cA_big, n*LL + l, k0, 0.f, 0.f);
        return;
    }
    const float* gi = g_gi + (size_t)(l*NN + n)*H3;
    const float* gh = g_gh + (size_t)n*H3;
    float2 gir = *(const float2*)(gi + k0);
    float2 giz = *(const float2*)(gi + HH + k0);
    float2 gin = *(const float2*)(gi + 2*HH + k0);
    float2 ghr = *(const float2*)(gh + k0);
    float2 ghz = *(const float2*)(gh + HH + k0);
    float2 ghn = *(const float2*)(gh + 2*HH + k0);
    float2 hp  = *(const float2*)(g_hprev + (size_t)n*HH + k0);
    float r0 = sigmoidf(gir.x + ghr.x), r1 = sigmoidf(gir.y + ghr.y);
    float z0 = sigmoidf(giz.x + ghz.x), z1 = sigmoidf(giz.y + ghz.y);
    float n0 = tanhf(gin.x + r0*ghn.x), n1 = tanhf(gin.y + r1*ghn.y);
    float h0 = (1.f - z0)*n0 + z0*hp.x;
    float h1 = (1.f - z1)*n1 + z1*hp.y;
    *(float2*)(g_h + (size_t)(l*NN + n)*HH + k0) = make_float2(h0, h1);
    *(float2*)(g_hprev + (size_t)n*HH + k0) = make_float2(h0, h1);
    storeA2(cA_h,   n,        k0, h0, h1);
    storeA2(cA_big, n*LL + l, k0, h0, h1);
}

// ---------------- K4: attention ----------------
#define ENC_PAD 68
__global__ __launch_bounds__(256) void k_attn(const float* __restrict__ enc_out,
                                              const int* __restrict__ lens){
    extern __shared__ float sm[];
    float* sh_h   = sm;
    float* sh_enc = sm + NSLOT*HH;
    float* sh_sc  = sh_enc + TT*ENC_PAD;
    __shared__ float red[8];
    __shared__ float s_mx, s_sum;

    int l  = blockIdx.x / BB;
    int bb = blockIdx.x % BB;
    int tid = threadIdx.x;
    int lane = tid & 31, wrp = tid >> 5;
    int t = tid;

    for (int i = tid; i < NSLOT*HH; i += 256){
        int s = i / HH, h = i % HH;
        sh_h[i] = g_h[(size_t)(l*NN + s*BB + bb)*HH + h];
    }
    for (int i = tid; i < NSLOT*TT; i += 256) sh_sc[i] = 0.f;
    __syncthreads();

    for (int kc = 0; kc < HH; kc += 64){
        int kw = min(64, HH - kc);
        for (int i = tid; i < TT*kw; i += 256){
            int tt2 = i / kw, kk = i % kw;
            sh_enc[tt2*ENC_PAD + kk] = enc_out[((size_t)bb*TT + tt2)*HH + kc + kk];
        }
        __syncthreads();
        for (int sg = 0; sg < NSLOT; sg += 10){
            float acc[10];
            #pragma unroll
            for (int u = 0; u < 10; u++) acc[u] = 0.f;
            for (int kk = 0; kk < kw; kk += 4){
                float4 e = *(const float4*)&sh_enc[t*ENC_PAD + kk];
                #pragma unroll
                for (int u = 0; u < 10; u++){
                    float4 hv = *(const float4*)&sh_h[(sg+u)*HH + kc + kk];
                    acc[u] += hv.x*e.x + hv.y*e.y + hv.z*e.z + hv.w*e.w;
                }
            }
            #pragma unroll
            for (int u = 0; u < 10; u++) sh_sc[(sg+u)*TT + t] += acc[u];
        }
        __syncthreads();
    }

    int len = lens[bb];
    for (int s = 0; s < NSLOT; s++){
        float v = (t < len) ? sh_sc[s*TT + t] : -1e9f;
        float m = warpMax(v);
        if (lane == 0) red[wrp] = m;
        __syncthreads();
        if (tid == 0){
            float mm = red[0];
            #pragma unroll
            for (int i = 1; i < 8; i++) mm = fmaxf(mm, red[i]);
            s_mx = mm;
        }
        __syncthreads();
        float p = expf(v - s_mx);
        float su = warpSum(p);
        if (lane == 0) red[wrp] = su;
        __syncthreads();
        if (tid == 0){
            float ss = 0.f;
            #pragma unroll
            for (int i = 0; i < 8; i++) ss += red[i];
            s_sum = ss;
        }
        __syncthreads();
        p /= s_sum;
        sh_sc[s*TT + t] = p;
        g_prob[(size_t)(l*NN + s*BB + bb)*TT + t] = p;
        __syncthreads();
    }

    for (int hc = 0; hc < HH; hc += 64){
        int hw = min(64, HH - hc);
        __syncthreads();
        for (int i = tid; i < TT*hw; i += 256){
            int tt2 = i / hw, hh = i % hw;
            sh_enc[tt2*ENC_PAD + hh] = enc_out[((size_t)bb*TT + tt2)*HH + hc + hh];
        }
        __syncthreads();
        int nq = NSLOT * (hw >> 2);
        for (int oi = tid; oi < nq; oi += 256){
            int s  = oi / (hw >> 2);
            int h4 = (oi % (hw >> 2)) * 4;
            float4 a = make_float4(0,0,0,0);
            for (int tt2 = 0; tt2 < TT; tt2++){
                float p = sh_sc[s*TT + tt2];
                float4 e = *(const float4*)&sh_enc[tt2*ENC_PAD + h4];
                a.x += p*e.x; a.y += p*e.y; a.z += p*e.z; a.w += p*e.w;
            }
            *(float4*)&g_ctx[(size_t)(l*NN + s*BB + bb)*HH + hc + h4] = a;
        }
    }
}

// ---------------- K5: switch ----------------
__global__ void k_switch(const float* __restrict__ w_ratio, const float* __restrict__ b_ratio){
    int row = blockIdx.x;
    int tid = threadIdx.x;
    const float* h = g_h      + (size_t)row*HH;
    const float* c = g_ctx    + (size_t)row*HH;
    const float* x = g_dec_in + (size_t)row*HH;
    float a = 0.f;
    for (int i = tid; i < HH; i += 128)
        a += h[i]*w_ratio[i] + c[i]*w_ratio[HH + i] + x[i]*w_ratio[2*HH + i];
    __shared__ float red[4];
    a = warpSum(a);
    if ((tid & 31) == 0) red[tid >> 5] = a;
    __syncthreads();
    if (tid == 0){
        float tot = red[0] + red[1] + red[2] + red[3] + b_ratio[0];
        g_switch[row] = sigmoidf(tot);
    }
}

// ---------------- K6: gates head ----------------
__global__ void k_gates(const float* __restrict__ w_gate, const float* __restrict__ b_gate,
                        float* __restrict__ out_gates){
    int n = blockIdx.x;
    int tid = threadIdx.x;
    const float* c = g_ctx + (size_t)n*HH;
    float a0 = 0.f, a1 = 0.f, a2 = 0.f;
    for (int i = tid; i < HH; i += 128){
        float cv = c[i];
        a0 += cv * w_gate[i];
        a1 += cv * w_gate[HH + i];
        a2 += cv * w_gate[2*HH + i];
    }
    __shared__ float red[3][4];
    a0 = warpSum(a0); a1 = warpSum(a1); a2 = warpSum(a2);
    if ((tid & 31) == 0){
        int w = tid >> 5;
        red[0][w] = a0; red[1][w] = a1; red[2][w] = a2;
    }
    __syncthreads();
    if (tid < GG){
        float tot = red[tid][0] + red[tid][1] + red[tid][2] + red[tid][3] + b_gate[tid];
        out_gates[(size_t)n*GG + tid] = tot;
    }
}

// ---------------- K8: softmax + scatter + mix, online (max,sum), 72KB smem ----
__global__ __launch_bounds__(256) void k_softmix(float* __restrict__ out,
                                                 const int* __restrict__ story){
    extern __shared__ float pctx[];   // VV floats only
    __shared__ float redm[8], reds[8];
    __shared__ float s_mx, s_sum;
    int m = blockIdx.x, tid = threadIdx.x;
    int lane = tid & 31, wrp = tid >> 5;
    int n = m / LL, l = m % LL, bb = n % BB;
    int rowa = l*NN + n;
    float sw = g_switch[rowa];

    for (int i = tid; i < VV; i += 256) pctx[i] = 0.f;
    __syncthreads();
    {
        float p = g_prob[(size_t)rowa*TT + tid];
        int c = story[bb*TT + tid];
        atomicAdd(&pctx[c], p);
    }

    // pass 1: online (max, sum) over logits
    float* base = out + (size_t)m*VV;
    float mt = -INFINITY, st = 0.f;
    for (int v = tid; v < VV; v += 256){
        float x = base[v];
        float nm = fmaxf(mt, x);
        st = st * __expf(mt - nm) + __expf(x - nm);
        mt = nm;
    }
    // warp combine
    #pragma unroll
    for (int o = 16; o; o >>= 1){
        float mo = __shfl_xor_sync(0xffffffffu, mt, o);
        float so = __shfl_xor_sync(0xffffffffu, st, o);
        float nm = fmaxf(mt, mo);
        st = st * __expf(mt - nm) + so * __expf(mo - nm);
        mt = nm;
    }
    if (lane == 0){ redm[wrp] = mt; reds[wrp] = st; }
    __syncthreads();
    if (tid == 0){
        float M = redm[0];
        #pragma unroll
        for (int i = 1; i < 8; i++) M = fmaxf(M, redm[i]);
        float S = 0.f;
        #pragma unroll
        for (int i = 0; i < 8; i++) S += reds[i] * __expf(redm[i] - M);
        s_mx = M; s_sum = S;
    }
    __syncthreads();
    float mx = s_mx;
    float scale = sw / s_sum;
    float osw = 1.f - sw;
    // pass 2: re-read (L2-hot) and write final
    for (int v = tid; v < VV; v += 256)
        base[v] = __expf(base[v] - mx) * scale + osw * pctx[v];
}

// ---------------- launch ----------------
extern "C" void kernel_launch(void* const* d_in, const int* in_sizes, int n_in,
                              void* d_out, int out_size){
    const float* enc_hidden = (const float*)d_in[0];
    const float* enc_out    = (const float*)d_in[1];
    const float* emb        = (const float*)d_in[2];
    const float* w_ih       = (const float*)d_in[3];
    const float* w_hh       = (const float*)d_in[4];
    const float* b_ih       = (const float*)d_in[5];
    const float* b_hh       = (const float*)d_in[6];
    const float* w_ratio    = (const float*)d_in[7];
    const float* b_ratio    = (const float*)d_in[8];
    const float* w_gate     = (const float*)d_in[9];
    const float* b_gate     = (const float*)d_in[10];
    const float* slot_emb   = (const float*)d_in[11];
    const int*   lens       = (const int*)d_in[12];
    const int*   story      = (const int*)d_in[13];
    const int*   tgt        = (const int*)d_in[14];
    const int*   dom        = (const int*)d_in[15];
    const int*   slo        = (const int*)d_in[16];
    float* out = (float*)d_out;

    float *p_gi, *p_gh;
    uint32_t *pA_dec, *pA_big, *pA_h, *pB_emb, *pB_wih, *pB_whh;
    cudaGetSymbolAddress((void**)&p_gi,    g_gi);
    cudaGetSymbolAddress((void**)&p_gh,    g_gh);
    cudaGetSymbolAddress((void**)&pA_dec,  cA_dec);
    cudaGetSymbolAddress((void**)&pA_big,  cA_big);
    cudaGetSymbolAddress((void**)&pA_h,    cA_h);
    cudaGetSymbolAddress((void**)&pB_emb,  cB_emb);
    cudaGetSymbolAddress((void**)&pB_wih,  cB_wih);
    cudaGetSymbolAddress((void**)&pB_whh,  cB_whh);

    const int ATTN_SMEM = (NSLOT*HH + TT*ENC_PAD + NSLOT*TT) * 4;
    const int SMX_SMEM  = VV*4;   // 72000
    cudaFuncSetAttribute(k_attn, cudaFuncAttributeMaxDynamicSharedMemorySize, ATTN_SMEM);
    cudaFuncSetAttribute(k_softmix, cudaFuncAttributeMaxDynamicSharedMemorySize, SMX_SMEM);
    cudaFuncSetAttribute((const void*)mma_gemm2<128,true>,  cudaFuncAttributeMaxDynamicSharedMemorySize, MG2_SMEM_128);
    cudaFuncSetAttribute((const void*)mma_gemm2<128,false>, cudaFuncAttributeMaxDynamicSharedMemorySize, MG2_SMEM_128);
    cudaFuncSetAttribute((const void*)mma_gemm2<64,true>,   cudaFuncAttributeMaxDynamicSharedMemorySize, MG2_SMEM_64);

    const int nq = NCH*8;
    const int HP = HH2/2;

    // 0) weight conversions
    conv_B<<<(NBN_EMB*128*nq + 255)/256, 256>>>(emb,  pB_emb, VV,  NBN_EMB*128);
    conv_B<<<(NBN_W  *128*nq + 255)/256, 256>>>(w_ih, pB_wih, H3,  NBN_W*128);
    conv_B<<<(NBN_W  *128*nq + 255)/256, 256>>>(w_hh, pB_whh, H3,  NBN_W*128);

    // 1) decoder inputs + h0
    k_decin<<<(LL*NN*HP + 255)/256, 256>>>(emb, slot_emb, dom, slo, tgt);
    k_hinit<<<(NN*HP + 255)/256, 256>>>(enc_hidden);

    // 2) input-side gates, all steps
    {
        dim3 grid(NBN_W, NBM_BIG);
        mma_gemm2<128,true><<<grid, 256, MG2_SMEM_128>>>(pA_dec, pB_wih, b_ih, p_gi, MM, H3, H3);
    }

    // 3) GRU recurrence
    for (int l = 0; l < LL; l++){
        dim3 grid((H3 + 63)/64, NBM_H);
        mma_gemm2<64,true><<<grid, 256, MG2_SMEM_64>>>(pA_h, pB_whh, b_hh, p_gh, NN, H3, H3);
        k_gate<<<(NN*HP + 255)/256, 256>>>(l);
    }

    // 4) attention
    k_attn<<<LL*BB, 256, ATTN_SMEM>>>(enc_out, lens);

    // 5) switch; 6) gates head
    k_switch<<<LL*NN, 128>>>(w_ratio, b_ratio);
    k_gates<<<NN, 128>>>(w_gate, b_gate, out + POINTS_ELEMS);

    // 7) big vocab GEMM (fp16), logits into d_out
    {
        dim3 grid(NBN_EMB, NBM_BIG);
        mma_gemm2<128,false><<<grid, 256, MG2_SMEM_128>>>(pA_big, pB_emb, nullptr, out, MM, VV, VV);
    }

    // 8) softmax + pointer scatter + mix, in place
    k_softmix<<<MM, 256, SMX_SMEM>>>(out, story);
}